// round 5
// baseline (speedup 1.0000x reference)
#include <cuda_runtime.h>
#include <cuda_fp16.h>
#include <math.h>
#include <stdint.h>

// ---------------- problem constants ----------------
#define NN     30000      // nodes
#define EMAX   480000     // edges (before self loops)
#define DIN    128
#define F1     256        // H1*DH
#define F2     64         // H2*DH
#define GG     64
#define DOUT   10
#define ETOT   (EMAX + NN)

// ---------------- scratch (device globals; no allocation allowed) ----------------
__device__ __half g_xl1h[NN * F1];   // fp16 gathered operand, layer 1
__device__ float  g_xr1 [NN * F1];
__device__ float  g_h1  [NN * F1];
__device__ __half g_xl2h[NN * F2];   // fp16 gathered operand, layer 2
__device__ float  g_xr2 [NN * F2];
__device__ float  g_h2  [NN * F2];
__device__ int    g_deg[NN + 1];
__device__ int    g_row[NN + 1];
__device__ int    g_cur[NN];
__device__ int    g_csr[ETOT];
__device__ float  g_pool[GG * F2];

// ---------------- tf32 mma.sync helpers (arch-agnostic PTX; works on sm_103) ----
__device__ __forceinline__ uint32_t f2tf32(float f) {
    uint32_t u;
    asm("cvt.rna.tf32.f32 %0, %1;" : "=r"(u) : "f"(f));
    return u;
}

__device__ __forceinline__ void mma_m16n8k8(float* d, const uint32_t* a, const uint32_t* b) {
    asm("mma.sync.aligned.m16n8k8.row.col.f32.tf32.tf32.f32 "
        "{%0,%1,%2,%3},{%4,%5,%6,%7},{%8,%9},{%0,%1,%2,%3};"
        : "+f"(d[0]), "+f"(d[1]), "+f"(d[2]), "+f"(d[3])
        : "r"(a[0]), "r"(a[1]), "r"(a[2]), "r"(a[3]), "r"(b[0]), "r"(b[1]));
}

// ---------------- tf32 tensor GEMM over concatenated [B0|B1] ------------------
// C(:, 0:Nn) = A@B0 -> stored fp16 to H0 ;  C(:, Nn:2Nn) = A@B1 -> fp32 to C1
// CTA 128x128, 8 warps in 2x4 grid, warp tile 64x32 (4x4 m16n8 frags), BK=32.
#define BKG 32
__global__ void __launch_bounds__(256) k_mma_gemm(const float* __restrict__ A,
                                                  const float* __restrict__ B0,
                                                  const float* __restrict__ B1,
                                                  __half* __restrict__ H0,
                                                  float* __restrict__ C1,
                                                  int M, int K, int Nn) {
    __shared__ uint32_t As[128][BKG + 4];   // pad 4 -> conflict-free frag loads
    __shared__ uint32_t Bs[128][BKG + 4];

    int n0 = blockIdx.x * 128;
    int m0 = blockIdx.y * 128;

    int tid  = threadIdx.x;
    int wid  = tid >> 5, lane = tid & 31;
    int g    = lane >> 2, t = lane & 3;
    int wm   = wid >> 2, wn = wid & 3;      // warp grid 2x4
    int wr   = wm * 64;
    int wc   = wn * 32;

    float acc[4][4][4];
#pragma unroll
    for (int i = 0; i < 4; i++)
#pragma unroll
        for (int j = 0; j < 4; j++)
#pragma unroll
            for (int q = 0; q < 4; q++) acc[i][j][q] = 0.f;

    // A load mapping
    int arow = tid >> 3;           // 0..31 per pass of 32 rows
    int ac4  = tid & 7;            // float4 col
    // B load mapping (per-column matrix select against concat width)
    int bn   = tid & 127;
    int bk2  = (tid >> 7) * 2;     // 0 or 2
    int cglb = n0 + bn;
    const float* Bp = (cglb < Nn) ? B0 : B1;
    int bc   = (cglb < Nn) ? cglb : cglb - Nn;

    for (int k0 = 0; k0 < K; k0 += BKG) {
        // stage global loads in registers (overlaps prior tile's MMAs)
        float4 a_st[4];
#pragma unroll
        for (int p = 0; p < 4; p++) {
            int gr = m0 + p * 32 + arow; if (gr >= M) gr = M - 1;
            a_st[p] = *(const float4*)(A + (size_t)gr * K + k0 + ac4 * 4);
        }
        float b_st[16];
#pragma unroll
        for (int q = 0; q < 8; q++) {
            int k = q * 4 + bk2;
            b_st[q * 2 + 0] = Bp[(size_t)(k0 + k) * Nn + bc];
            b_st[q * 2 + 1] = Bp[(size_t)(k0 + k + 1) * Nn + bc];
        }
        __syncthreads();   // prior compute done, smem free
#pragma unroll
        for (int p = 0; p < 4; p++) {
            int r = p * 32 + arow;
            uint4 u = make_uint4(f2tf32(a_st[p].x), f2tf32(a_st[p].y),
                                 f2tf32(a_st[p].z), f2tf32(a_st[p].w));
            *(uint4*)&As[r][ac4 * 4] = u;
        }
#pragma unroll
        for (int q = 0; q < 8; q++) {
            int k = q * 4 + bk2;
            uint2 u = make_uint2(f2tf32(b_st[q * 2]), f2tf32(b_st[q * 2 + 1]));
            *(uint2*)&Bs[bn][k] = u;
        }
        __syncthreads();

#pragma unroll
        for (int ks = 0; ks < BKG / 8; ks++) {
            int kk = ks * 8;
            uint32_t af[4][4], bf[4][2];
#pragma unroll
            for (int mt = 0; mt < 4; mt++) {
                int r = wr + mt * 16 + g;
                af[mt][0] = As[r][kk + t];
                af[mt][1] = As[r + 8][kk + t];
                af[mt][2] = As[r][kk + t + 4];
                af[mt][3] = As[r + 8][kk + t + 4];
            }
#pragma unroll
            for (int nt = 0; nt < 4; nt++) {
                int n = wc + nt * 8 + g;
                bf[nt][0] = Bs[n][kk + t];
                bf[nt][1] = Bs[n][kk + t + 4];
            }
#pragma unroll
            for (int mt = 0; mt < 4; mt++)
#pragma unroll
                for (int nt = 0; nt < 4; nt++)
                    mma_m16n8k8(acc[mt][nt], af[mt], bf[nt]);
        }
    }

    // epilogue: left half -> fp16 H0, right half -> fp32 C1
#pragma unroll
    for (int mt = 0; mt < 4; mt++) {
        int r0 = m0 + wr + mt * 16 + g;
        int r1 = r0 + 8;
#pragma unroll
        for (int nt = 0; nt < 4; nt++) {
            int cc = n0 + wc + nt * 8 + t * 2;
            if (cc < Nn) {
                __half2 h01 = __floats2half2_rn(acc[mt][nt][0], acc[mt][nt][1]);
                __half2 h23 = __floats2half2_rn(acc[mt][nt][2], acc[mt][nt][3]);
                if (r0 < M) *(__half2*)(H0 + (size_t)r0 * Nn + cc) = h01;
                if (r1 < M) *(__half2*)(H0 + (size_t)r1 * Nn + cc) = h23;
            } else {
                int c2 = cc - Nn;
                if (r0 < M)
                    *(float2*)(C1 + (size_t)r0 * Nn + c2) = make_float2(acc[mt][nt][0], acc[mt][nt][1]);
                if (r1 < M)
                    *(float2*)(C1 + (size_t)r1 * Nn + c2) = make_float2(acc[mt][nt][2], acc[mt][nt][3]);
            }
        }
    }
}

// ---------------- CSR build ----------------
__global__ void k_init_deg(int n) {
    int i = blockIdx.x * blockDim.x + threadIdx.x;
    if (i < n) g_deg[i] = 1;   // self loop
}

__global__ void k_hist(const int* __restrict__ ei, int E) {
    int e = blockIdx.x * blockDim.x + threadIdx.x;
    if (e < E) atomicAdd(&g_deg[ei[E + e]], 1);
}

// 1024-thread shuffle-based exclusive scan
__global__ void k_scan(int n) {
    __shared__ int wsum[32];
    __shared__ int carry;
    int tid = threadIdx.x, lane = tid & 31, wid = tid >> 5;
    if (tid == 0) carry = 0;
    __syncthreads();
    for (int base = 0; base < n; base += 1024) {
        int i = base + tid;
        int v = (i < n) ? g_deg[i] : 0;
        int incl = v;
#pragma unroll
        for (int off = 1; off < 32; off <<= 1) {
            int tt = __shfl_up_sync(0xffffffffu, incl, off);
            if (lane >= off) incl += tt;
        }
        if (lane == 31) wsum[wid] = incl;
        __syncthreads();
        if (wid == 0) {
            int s = wsum[lane];
#pragma unroll
            for (int off = 1; off < 32; off <<= 1) {
                int tt = __shfl_up_sync(0xffffffffu, s, off);
                if (lane >= off) s += tt;
            }
            wsum[lane] = s;
        }
        __syncthreads();
        int woff = wid ? wsum[wid - 1] : 0;
        int c = carry;
        if (i < n) g_row[i] = c + woff + incl - v;
        __syncthreads();
        if (tid == 0) carry = c + wsum[31];
        __syncthreads();
    }
    if (tid == 0) g_row[n] = carry;
}

__global__ void k_csr_init(int n) {
    int i = blockIdx.x * blockDim.x + threadIdx.x;
    if (i < n) {
        int r = g_row[i];
        g_csr[r] = i;
        g_cur[i] = r + 1;
    }
}

__global__ void k_scatter(const int* __restrict__ ei, int E) {
    int e = blockIdx.x * blockDim.x + threadIdx.x;
    if (e < E) {
        int dst = ei[E + e];
        int pos = atomicAdd(&g_cur[dst], 1);
        g_csr[pos] = ei[e];
    }
}

// ---------------- GATv2 aggregation, layer 1 (fp16 gather) -------------------
__global__ void k_agg1(const float* __restrict__ att, const float* __restrict__ bias) {
    int warp = (blockIdx.x * blockDim.x + threadIdx.x) >> 5;
    if (warp >= NN) return;
    int lane = threadIdx.x & 31;
    int base = (lane >> 2) * 32 + (lane & 3) * 8;

    float xr[8], av[8];
    {
        float4 r0 = *(const float4*)(g_xr1 + (size_t)warp * F1 + base);
        float4 r1 = *(const float4*)(g_xr1 + (size_t)warp * F1 + base + 4);
        xr[0]=r0.x; xr[1]=r0.y; xr[2]=r0.z; xr[3]=r0.w;
        xr[4]=r1.x; xr[5]=r1.y; xr[6]=r1.z; xr[7]=r1.w;
        float4 a0 = *(const float4*)(att + base);
        float4 a1 = *(const float4*)(att + base + 4);
        av[0]=a0.x; av[1]=a0.y; av[2]=a0.z; av[3]=a0.w;
        av[4]=a1.x; av[5]=a1.y; av[6]=a1.z; av[7]=a1.w;
    }

    float acc[8];
#pragma unroll
    for (int j = 0; j < 8; j++) acc[j] = 0.f;
    float m = -3.0e38f, z = 0.f;

    const __half* xb = g_xl1h + base;
    int e0 = g_row[warp], e1 = g_row[warp + 1];
    uint4 nu = *(const uint4*)(xb + (size_t)g_csr[e0] * F1);
    for (int e = e0; e < e1; e++) {
        uint4 u = nu;
        if (e + 1 < e1)
            nu = *(const uint4*)(xb + (size_t)g_csr[e + 1] * F1);
        __half2* hh = (__half2*)&u;
        float2 p0 = __half22float2(hh[0]);
        float2 p1 = __half22float2(hh[1]);
        float2 p2 = __half22float2(hh[2]);
        float2 p3 = __half22float2(hh[3]);
        float xj[8] = {p0.x, p0.y, p1.x, p1.y, p2.x, p2.y, p3.x, p3.y};
        float t = 0.f;
#pragma unroll
        for (int j = 0; j < 8; j++) {
            float v = xj[j] + xr[j];
            v = (v > 0.f) ? v : 0.2f * v;
            t = fmaf(v, av[j], t);
        }
        t += __shfl_xor_sync(0xffffffffu, t, 1);
        t += __shfl_xor_sync(0xffffffffu, t, 2);
        float mn = fmaxf(m, t);
        float sc = __expf(m - mn);
        float w  = __expf(t - mn);
        z = z * sc + w;
#pragma unroll
        for (int j = 0; j < 8; j++)
            acc[j] = fmaf(acc[j], sc, w * xj[j]);
        m = mn;
    }
    float inv = 1.f / z;
    float* out = g_h1 + (size_t)warp * F1 + base;
#pragma unroll
    for (int j = 0; j < 8; j++) {
        float v = acc[j] * inv + bias[base + j];
        out[j] = (v > 0.f) ? v : expm1f(v);        // ELU fused
    }
}

// ---------------- GATv2 aggregation, layer 2 (fp16 gather) -------------------
__global__ void k_agg2(const float* __restrict__ att, const float* __restrict__ bias) {
    int warp = (blockIdx.x * blockDim.x + threadIdx.x) >> 5;
    if (warp >= NN) return;
    int lane = threadIdx.x & 31;
    int base = (lane >> 4) * 32 + (lane & 15) * 2;

    float2 xr = *(const float2*)(g_xr2 + (size_t)warp * F2 + base);
    float2 av = *(const float2*)(att + base);

    float acc0 = 0.f, acc1 = 0.f;
    float m = -3.0e38f, z = 0.f;

    const __half* xb = g_xl2h + base;
    int e0 = g_row[warp], e1 = g_row[warp + 1];
    __half2 nx = *(const __half2*)(xb + (size_t)g_csr[e0] * F2);
    for (int e = e0; e < e1; e++) {
        float2 xj = __half22float2(nx);
        if (e + 1 < e1)
            nx = *(const __half2*)(xb + (size_t)g_csr[e + 1] * F2);
        float v0 = xj.x + xr.x; v0 = (v0 > 0.f) ? v0 : 0.2f * v0;
        float v1 = xj.y + xr.y; v1 = (v1 > 0.f) ? v1 : 0.2f * v1;
        float t = fmaf(v0, av.x, v1 * av.y);
        t += __shfl_xor_sync(0xffffffffu, t, 1);
        t += __shfl_xor_sync(0xffffffffu, t, 2);
        t += __shfl_xor_sync(0xffffffffu, t, 4);
        t += __shfl_xor_sync(0xffffffffu, t, 8);
        float mn = fmaxf(m, t);
        float sc = __expf(m - mn);
        float w  = __expf(t - mn);
        z = z * sc + w;
        acc0 = fmaf(acc0, sc, w * xj.x);
        acc1 = fmaf(acc1, sc, w * xj.y);
        m = mn;
    }
    float inv = 1.f / z;
    g_h2[(size_t)warp * F2 + base + 0] = acc0 * inv + bias[base + 0];
    g_h2[(size_t)warp * F2 + base + 1] = acc1 * inv + bias[base + 1];
}

// ---------------- mean pool over sorted batch ----------------
__device__ __forceinline__ int lb(const int* b, int n, int g) {
    int lo = 0, hi = n;
    while (lo < hi) { int mid = (lo + hi) >> 1; if (b[mid] < g) lo = mid + 1; else hi = mid; }
    return lo;
}

__global__ void k_pool(const int* __restrict__ batch, int n) {
    __shared__ float part[4][64];
    int g = blockIdx.x;            // 64 blocks x 256 threads
    int d = threadIdx.x & 63;
    int ty = threadIdx.x >> 6;     // 0..3
    int s = lb(batch, n, g);
    int e = lb(batch, n, g + 1);
    float sum = 0.f;
    for (int i = s + ty; i < e; i += 4) sum += g_h2[(size_t)i * F2 + d];
    part[ty][d] = sum;
    __syncthreads();
    if (ty == 0) {
        float tot = part[0][d] + part[1][d] + part[2][d] + part[3][d];
        int cnt = e - s; if (cnt < 1) cnt = 1;
        g_pool[g * F2 + d] = tot / (float)cnt;
    }
}

// ---------------- MLP head ----------------
__global__ void k_mlp(const float* __restrict__ fc1w, const float* __restrict__ fc1b,
                      const float* __restrict__ fc2w, const float* __restrict__ fc2b,
                      const float* __restrict__ fcw,  const float* __restrict__ fcb,
                      float* __restrict__ out) {
    __shared__ float hg[GG * 64];
    __shared__ float x1[GG * 32];
    __shared__ float x2[GG * 16];
    int tid = threadIdx.x;
    for (int i = tid; i < GG * 64; i += 256) hg[i] = g_pool[i];
    __syncthreads();
    for (int i = tid; i < GG * 32; i += 256) {
        int g = i >> 5, o = i & 31;
        float s = fc1b[o];
        for (int k = 0; k < 64; k++) s = fmaf(hg[g * 64 + k], fc1w[k * 32 + o], s);
        x1[i] = fmaxf(s, 0.f);
    }
    __syncthreads();
    for (int i = tid; i < GG * 16; i += 256) {
        int g = i >> 4, o = i & 15;
        float s = fc2b[o];
        for (int k = 0; k < 32; k++) s = fmaf(x1[g * 32 + k], fc2w[k * 16 + o], s);
        float v = fmaxf(s, 0.f);
        x2[i] = v;
        out[GG * DOUT + i] = v;
    }
    __syncthreads();
    for (int i = tid; i < GG * DOUT; i += 256) {
        int g = i / DOUT, o = i - g * DOUT;
        float s = fcb[o];
        for (int k = 0; k < 16; k++) s = fmaf(x2[g * 16 + k], fcw[k * DOUT + o], s);
        out[i] = s;
    }
}

// ---------------- launch ----------------
extern "C" void kernel_launch(void* const* d_in, const int* in_sizes, int n_in,
                              void* d_out, int out_size) {
    const float* x    = (const float*)d_in[0];
    const int*   ei   = (const int*)  d_in[1];
    const int*   bat  = (const int*)  d_in[2];
    const float* W1l  = (const float*)d_in[3];
    const float* W1r  = (const float*)d_in[4];
    const float* a1   = (const float*)d_in[5];
    const float* b1   = (const float*)d_in[6];
    const float* W2l  = (const float*)d_in[7];
    const float* W2r  = (const float*)d_in[8];
    const float* a2   = (const float*)d_in[9];
    const float* b2   = (const float*)d_in[10];
    const float* fc1w = (const float*)d_in[11];
    const float* fc1b = (const float*)d_in[12];
    const float* fc2w = (const float*)d_in[13];
    const float* fc2b = (const float*)d_in[14];
    const float* fcw  = (const float*)d_in[15];
    const float* fcb  = (const float*)d_in[16];
    float* out = (float*)d_out;

    int E = in_sizes[1] / 2;

    __half *xl1h, *xl2h;
    float *xr1, *h1, *xr2;
    cudaGetSymbolAddress((void**)&xl1h, g_xl1h);
    cudaGetSymbolAddress((void**)&xr1,  g_xr1);
    cudaGetSymbolAddress((void**)&h1,   g_h1);
    cudaGetSymbolAddress((void**)&xl2h, g_xl2h);
    cudaGetSymbolAddress((void**)&xr2,  g_xr2);

    const int GRID_M = (NN + 127) / 128;   // 235

    // CSR front half (independent of GEMM)
    k_init_deg<<<(NN + 255) / 256, 256>>>(NN);            // launch 0
    k_hist<<<(E + 255) / 256, 256>>>(ei, E);              // launch 1
    k_scan<<<1, 1024>>>(NN);                              // launch 2

    // layer 1 linear transforms (launch 3 -> ncu capture window)
    k_mma_gemm<<<dim3(2 * F1 / 128, GRID_M), 256>>>(x, W1l, W1r, xl1h, xr1,
                                                    NN, DIN, F1);

    // CSR back half
    k_csr_init<<<(NN + 255) / 256, 256>>>(NN);            // launch 4
    k_scatter<<<(E + 255) / 256, 256>>>(ei, E);           // launch 5

    // layer 1 attention + aggregation (+ELU fused)
    k_agg1<<<(NN * 32 + 255) / 256, 256>>>(a1, b1);       // launch 6

    // layer 2 linear transforms
    k_mma_gemm<<<dim3(2 * F2 / 128, GRID_M), 256>>>(h1, W2l, W2r, xl2h, xr2,
                                                    NN, F1, F2);

    // layer 2 attention + aggregation (+bias)
    k_agg2<<<(NN * 32 + 255) / 256, 256>>>(a2, b2);

    // pool + MLP head
    k_pool<<<GG, 256>>>(bat, NN);
    k_mlp<<<1, 256>>>(fc1w, fc1b, fc2w, fc2b, fcw, fcb, out);
}

// round 6
// speedup vs baseline: 1.1437x; 1.1437x over previous
#include <cuda_runtime.h>
#include <cuda_fp16.h>
#include <math.h>
#include <stdint.h>

// ---------------- problem constants ----------------
#define NN     30000      // nodes
#define EMAX   480000     // edges (before self loops)
#define DIN    128
#define F1     256        // H1*DH
#define F2     64         // H2*DH
#define GG     64
#define DOUT   10
#define ETOT   (EMAX + NN)

// ---------------- scratch (device globals; no allocation allowed) ----------------
__device__ __half g_xl1h[NN * F1];   // fp16 gathered operand, layer 1
__device__ float  g_xr1 [NN * F1];
__device__ __half g_h1  [NN * F1];   // fp16: only feeds GEMM2 A
__device__ __half g_xl2h[NN * F2];   // fp16 gathered operand, layer 2
__device__ float  g_xr2 [NN * F2];
__device__ float  g_h2  [NN * F2];
__device__ int    g_deg[NN + 1];
__device__ int    g_row[NN + 1];
__device__ int    g_cur[NN];
__device__ int    g_csr[ETOT];
__device__ float  g_pool[GG * F2];

// ---------------- fp16 mma.sync helpers ----------------
__device__ __forceinline__ void mma_f16(float* d, const uint32_t* a, const uint32_t* b) {
    asm("mma.sync.aligned.m16n8k16.row.col.f32.f16.f16.f32 "
        "{%0,%1,%2,%3},{%4,%5,%6,%7},{%8,%9},{%0,%1,%2,%3};"
        : "+f"(d[0]), "+f"(d[1]), "+f"(d[2]), "+f"(d[3])
        : "r"(a[0]), "r"(a[1]), "r"(a[2]), "r"(a[3]), "r"(b[0]), "r"(b[1]));
}

// A-row loaders: 4 half-pairs (8 bytes smem) from either fp32 or fp16 source
__device__ __forceinline__ void load_a4h2(const float* A, size_t idx, uint32_t* d) {
    float4 v = *(const float4*)(A + idx);
    __half2 h0 = __floats2half2_rn(v.x, v.y);
    __half2 h1 = __floats2half2_rn(v.z, v.w);
    d[0] = *(uint32_t*)&h0;
    d[1] = *(uint32_t*)&h1;
}
__device__ __forceinline__ void load_a4h2(const __half* A, size_t idx, uint32_t* d) {
    uint2 u = *(const uint2*)(A + idx);
    d[0] = u.x; d[1] = u.y;
}

// ---------------- fp16 tensor GEMM (dual-B): C[M,N] = A[M,K] @ B[K,N] ---------
// 256 thr, BM=128, BN=64, BK=32; warps 4x2; warp tile 32x32 (2x4 m16n8k16 frags)
// grid.x = 2*(Nn/64): first half B0 -> H0 (fp16), second half B1 -> C1 (fp32).
#define BKG 32
template<typename TA>
__global__ void __launch_bounds__(256) k_hgemm(const TA* __restrict__ A,
                                               const float* __restrict__ B0,
                                               const float* __restrict__ B1,
                                               __half* __restrict__ H0,
                                               float* __restrict__ C1,
                                               int M, int K, int Nn) {
    __shared__ uint32_t As[128][20];   // 16 half2 cols + pad4 -> conflict-free frags
    __shared__ uint32_t Bs[64][21];    // 16 half2 cols + pad5 -> conflict-free stores

    int bx = blockIdx.x;
    int nblk = gridDim.x >> 1;
    bool left = bx < nblk;
    const float* B = left ? B0 : B1;
    if (!left) bx -= nblk;
    int n0 = bx * 64;
    int m0 = blockIdx.y * 128;

    int tid  = threadIdx.x;
    int wid  = tid >> 5, lane = tid & 31;
    int g    = lane >> 2, t = lane & 3;
    int wm   = wid >> 1, wn = wid & 1;      // warp grid 4x2
    int wr   = wm * 32;
    int wc   = wn * 32;

    float acc[2][4][4];
#pragma unroll
    for (int i = 0; i < 2; i++)
#pragma unroll
        for (int j = 0; j < 4; j++)
#pragma unroll
            for (int q = 0; q < 4; q++) acc[i][j][q] = 0.f;

    int arow = tid >> 3;           // 0..31 per pass of 32 rows
    int ac   = tid & 7;            // 8 threads/row, each 4 halves
    int bn   = tid & 63;
    int bk2b = tid >> 6;           // 0..3

    for (int k0 = 0; k0 < K; k0 += BKG) {
        // A tile: 128 x 32 -> fp16 smem
#pragma unroll
        for (int p = 0; p < 4; p++) {
            int r = p * 32 + arow;
            int gr = m0 + r; if (gr >= M) gr = M - 1;
            uint32_t d2[2];
            load_a4h2(A, (size_t)gr * K + k0 + ac * 4, d2);
            *(uint2*)&As[r][ac * 2] = make_uint2(d2[0], d2[1]);
        }
        // B tile: 32 x 64 from [K,N] -> transposed fp16 Bs[n][k2]
#pragma unroll
        for (int j = 0; j < 4; j++) {
            int k2 = bk2b + j * 4;
            float f0 = B[(size_t)(k0 + 2 * k2) * Nn + n0 + bn];
            float f1 = B[(size_t)(k0 + 2 * k2 + 1) * Nn + n0 + bn];
            __half2 h = __floats2half2_rn(f0, f1);
            Bs[bn][k2] = *(uint32_t*)&h;
        }
        __syncthreads();

#pragma unroll
        for (int ks = 0; ks < BKG / 16; ks++) {
            int kk2 = ks * 8;
            uint32_t af[2][4], bf[4][2];
#pragma unroll
            for (int mt = 0; mt < 2; mt++) {
                int r = wr + mt * 16 + g;
                af[mt][0] = As[r][kk2 + t];
                af[mt][1] = As[r + 8][kk2 + t];
                af[mt][2] = As[r][kk2 + t + 4];
                af[mt][3] = As[r + 8][kk2 + t + 4];
            }
#pragma unroll
            for (int nt = 0; nt < 4; nt++) {
                int n = wc + nt * 8 + g;
                bf[nt][0] = Bs[n][kk2 + t];
                bf[nt][1] = Bs[n][kk2 + t + 4];
            }
#pragma unroll
            for (int mt = 0; mt < 2; mt++)
#pragma unroll
                for (int nt = 0; nt < 4; nt++)
                    mma_f16(acc[mt][nt], af[mt], bf[nt]);
        }
        __syncthreads();
    }

    // epilogue: left block -> fp16 H0, right block -> fp32 C1
#pragma unroll
    for (int mt = 0; mt < 2; mt++) {
        int r0 = m0 + wr + mt * 16 + g;
        int r1 = r0 + 8;
#pragma unroll
        for (int nt = 0; nt < 4; nt++) {
            int cc = n0 + wc + nt * 8 + t * 2;
            if (left) {
                __half2 h01 = __floats2half2_rn(acc[mt][nt][0], acc[mt][nt][1]);
                __half2 h23 = __floats2half2_rn(acc[mt][nt][2], acc[mt][nt][3]);
                if (r0 < M) *(__half2*)(H0 + (size_t)r0 * Nn + cc) = h01;
                if (r1 < M) *(__half2*)(H0 + (size_t)r1 * Nn + cc) = h23;
            } else {
                if (r0 < M)
                    *(float2*)(C1 + (size_t)r0 * Nn + cc) = make_float2(acc[mt][nt][0], acc[mt][nt][1]);
                if (r1 < M)
                    *(float2*)(C1 + (size_t)r1 * Nn + cc) = make_float2(acc[mt][nt][2], acc[mt][nt][3]);
            }
        }
    }
}

// ---------------- CSR build ----------------
__global__ void k_init_deg(int n) {
    int i = blockIdx.x * blockDim.x + threadIdx.x;
    if (i < n) g_deg[i] = 1;   // self loop
}

__global__ void k_hist(const int* __restrict__ ei, int E) {
    int e = blockIdx.x * blockDim.x + threadIdx.x;
    if (e < E) atomicAdd(&g_deg[ei[E + e]], 1);
}

// 1024-thread shuffle-based exclusive scan
__global__ void k_scan(int n) {
    __shared__ int wsum[32];
    __shared__ int carry;
    int tid = threadIdx.x, lane = tid & 31, wid = tid >> 5;
    if (tid == 0) carry = 0;
    __syncthreads();
    for (int base = 0; base < n; base += 1024) {
        int i = base + tid;
        int v = (i < n) ? g_deg[i] : 0;
        int incl = v;
#pragma unroll
        for (int off = 1; off < 32; off <<= 1) {
            int tt = __shfl_up_sync(0xffffffffu, incl, off);
            if (lane >= off) incl += tt;
        }
        if (lane == 31) wsum[wid] = incl;
        __syncthreads();
        if (wid == 0) {
            int s = wsum[lane];
#pragma unroll
            for (int off = 1; off < 32; off <<= 1) {
                int tt = __shfl_up_sync(0xffffffffu, s, off);
                if (lane >= off) s += tt;
            }
            wsum[lane] = s;
        }
        __syncthreads();
        int woff = wid ? wsum[wid - 1] : 0;
        int c = carry;
        if (i < n) g_row[i] = c + woff + incl - v;
        __syncthreads();
        if (tid == 0) carry = c + wsum[31];
        __syncthreads();
    }
    if (tid == 0) g_row[n] = carry;
}

__global__ void k_csr_init(int n) {
    int i = blockIdx.x * blockDim.x + threadIdx.x;
    if (i < n) {
        int r = g_row[i];
        g_csr[r] = i;
        g_cur[i] = r + 1;
    }
}

__global__ void k_scatter(const int* __restrict__ ei, int E) {
    int e = blockIdx.x * blockDim.x + threadIdx.x;
    if (e < E) {
        int dst = ei[E + e];
        int pos = atomicAdd(&g_cur[dst], 1);
        g_csr[pos] = ei[e];
    }
}

// ---------------- GATv2 aggregation, layer 1 (fp16 gather, fp16 h1 out) ------
__global__ void k_agg1(const float* __restrict__ att, const float* __restrict__ bias) {
    int warp = (blockIdx.x * blockDim.x + threadIdx.x) >> 5;
    if (warp >= NN) return;
    int lane = threadIdx.x & 31;
    int base = (lane >> 2) * 32 + (lane & 3) * 8;

    float xr[8], av[8];
    {
        float4 r0 = *(const float4*)(g_xr1 + (size_t)warp * F1 + base);
        float4 r1 = *(const float4*)(g_xr1 + (size_t)warp * F1 + base + 4);
        xr[0]=r0.x; xr[1]=r0.y; xr[2]=r0.z; xr[3]=r0.w;
        xr[4]=r1.x; xr[5]=r1.y; xr[6]=r1.z; xr[7]=r1.w;
        float4 a0 = *(const float4*)(att + base);
        float4 a1 = *(const float4*)(att + base + 4);
        av[0]=a0.x; av[1]=a0.y; av[2]=a0.z; av[3]=a0.w;
        av[4]=a1.x; av[5]=a1.y; av[6]=a1.z; av[7]=a1.w;
    }

    float acc[8];
#pragma unroll
    for (int j = 0; j < 8; j++) acc[j] = 0.f;
    float m = -3.0e38f, z = 0.f;

    const __half* xb = g_xl1h + base;
    int e0 = g_row[warp], e1 = g_row[warp + 1];
    uint4 nu = *(const uint4*)(xb + (size_t)g_csr[e0] * F1);
    for (int e = e0; e < e1; e++) {
        uint4 u = nu;
        if (e + 1 < e1)
            nu = *(const uint4*)(xb + (size_t)g_csr[e + 1] * F1);
        __half2* hh = (__half2*)&u;
        float2 p0 = __half22float2(hh[0]);
        float2 p1 = __half22float2(hh[1]);
        float2 p2 = __half22float2(hh[2]);
        float2 p3 = __half22float2(hh[3]);
        float xj[8] = {p0.x, p0.y, p1.x, p1.y, p2.x, p2.y, p3.x, p3.y};
        float t = 0.f;
#pragma unroll
        for (int j = 0; j < 8; j++) {
            float v = xj[j] + xr[j];
            v = (v > 0.f) ? v : 0.2f * v;
            t = fmaf(v, av[j], t);
        }
        t += __shfl_xor_sync(0xffffffffu, t, 1);
        t += __shfl_xor_sync(0xffffffffu, t, 2);
        float mn = fmaxf(m, t);
        float sc = __expf(m - mn);
        float w  = __expf(t - mn);
        z = z * sc + w;
#pragma unroll
        for (int j = 0; j < 8; j++)
            acc[j] = fmaf(acc[j], sc, w * xj[j]);
        m = mn;
    }
    float inv = 1.f / z;
    float o[8];
#pragma unroll
    for (int j = 0; j < 8; j++) {
        float v = acc[j] * inv + bias[base + j];
        o[j] = (v > 0.f) ? v : expm1f(v);          // ELU fused
    }
    __half2 h0 = __floats2half2_rn(o[0], o[1]);
    __half2 h1 = __floats2half2_rn(o[2], o[3]);
    __half2 h2 = __floats2half2_rn(o[4], o[5]);
    __half2 h3 = __floats2half2_rn(o[6], o[7]);
    uint4 uo = make_uint4(*(uint32_t*)&h0, *(uint32_t*)&h1,
                          *(uint32_t*)&h2, *(uint32_t*)&h3);
    *(uint4*)(g_h1 + (size_t)warp * F1 + base) = uo;
}

// ---------------- GATv2 aggregation, layer 2 (fp16 gather) -------------------
__global__ void k_agg2(const float* __restrict__ att, const float* __restrict__ bias) {
    int warp = (blockIdx.x * blockDim.x + threadIdx.x) >> 5;
    if (warp >= NN) return;
    int lane = threadIdx.x & 31;
    int base = (lane >> 4) * 32 + (lane & 15) * 2;

    float2 xr = *(const float2*)(g_xr2 + (size_t)warp * F2 + base);
    float2 av = *(const float2*)(att + base);

    float acc0 = 0.f, acc1 = 0.f;
    float m = -3.0e38f, z = 0.f;

    const __half* xb = g_xl2h + base;
    int e0 = g_row[warp], e1 = g_row[warp + 1];
    __half2 nx = *(const __half2*)(xb + (size_t)g_csr[e0] * F2);
    for (int e = e0; e < e1; e++) {
        float2 xj = __half22float2(nx);
        if (e + 1 < e1)
            nx = *(const __half2*)(xb + (size_t)g_csr[e + 1] * F2);
        float v0 = xj.x + xr.x; v0 = (v0 > 0.f) ? v0 : 0.2f * v0;
        float v1 = xj.y + xr.y; v1 = (v1 > 0.f) ? v1 : 0.2f * v1;
        float t = fmaf(v0, av.x, v1 * av.y);
        t += __shfl_xor_sync(0xffffffffu, t, 1);
        t += __shfl_xor_sync(0xffffffffu, t, 2);
        t += __shfl_xor_sync(0xffffffffu, t, 4);
        t += __shfl_xor_sync(0xffffffffu, t, 8);
        float mn = fmaxf(m, t);
        float sc = __expf(m - mn);
        float w  = __expf(t - mn);
        z = z * sc + w;
        acc0 = fmaf(acc0, sc, w * xj.x);
        acc1 = fmaf(acc1, sc, w * xj.y);
        m = mn;
    }
    float inv = 1.f / z;
    g_h2[(size_t)warp * F2 + base + 0] = acc0 * inv + bias[base + 0];
    g_h2[(size_t)warp * F2 + base + 1] = acc1 * inv + bias[base + 1];
}

// ---------------- mean pool over sorted batch ----------------
__device__ __forceinline__ int lb(const int* b, int n, int g) {
    int lo = 0, hi = n;
    while (lo < hi) { int mid = (lo + hi) >> 1; if (b[mid] < g) lo = mid + 1; else hi = mid; }
    return lo;
}

__global__ void k_pool(const int* __restrict__ batch, int n) {
    __shared__ float part[4][64];
    int g = blockIdx.x;            // 64 blocks x 256 threads
    int d = threadIdx.x & 63;
    int ty = threadIdx.x >> 6;     // 0..3
    int s = lb(batch, n, g);
    int e = lb(batch, n, g + 1);
    float sum = 0.f;
    for (int i = s + ty; i < e; i += 4) sum += g_h2[(size_t)i * F2 + d];
    part[ty][d] = sum;
    __syncthreads();
    if (ty == 0) {
        float tot = part[0][d] + part[1][d] + part[2][d] + part[3][d];
        int cnt = e - s; if (cnt < 1) cnt = 1;
        g_pool[g * F2 + d] = tot / (float)cnt;
    }
}

// ---------------- MLP head ----------------
__global__ void k_mlp(const float* __restrict__ fc1w, const float* __restrict__ fc1b,
                      const float* __restrict__ fc2w, const float* __restrict__ fc2b,
                      const float* __restrict__ fcw,  const float* __restrict__ fcb,
                      float* __restrict__ out) {
    __shared__ float hg[GG * 64];
    __shared__ float x1[GG * 32];
    __shared__ float x2[GG * 16];
    int tid = threadIdx.x;
    for (int i = tid; i < GG * 64; i += 256) hg[i] = g_pool[i];
    __syncthreads();
    for (int i = tid; i < GG * 32; i += 256) {
        int g = i >> 5, o = i & 31;
        float s = fc1b[o];
        for (int k = 0; k < 64; k++) s = fmaf(hg[g * 64 + k], fc1w[k * 32 + o], s);
        x1[i] = fmaxf(s, 0.f);
    }
    __syncthreads();
    for (int i = tid; i < GG * 16; i += 256) {
        int g = i >> 4, o = i & 15;
        float s = fc2b[o];
        for (int k = 0; k < 32; k++) s = fmaf(x1[g * 32 + k], fc2w[k * 16 + o], s);
        float v = fmaxf(s, 0.f);
        x2[i] = v;
        out[GG * DOUT + i] = v;
    }
    __syncthreads();
    for (int i = tid; i < GG * DOUT; i += 256) {
        int g = i / DOUT, o = i - g * DOUT;
        float s = fcb[o];
        for (int k = 0; k < 16; k++) s = fmaf(x2[g * 16 + k], fcw[k * DOUT + o], s);
        out[i] = s;
    }
}

// ---------------- launch ----------------
extern "C" void kernel_launch(void* const* d_in, const int* in_sizes, int n_in,
                              void* d_out, int out_size) {
    const float* x    = (const float*)d_in[0];
    const int*   ei   = (const int*)  d_in[1];
    const int*   bat  = (const int*)  d_in[2];
    const float* W1l  = (const float*)d_in[3];
    const float* W1r  = (const float*)d_in[4];
    const float* a1   = (const float*)d_in[5];
    const float* b1   = (const float*)d_in[6];
    const float* W2l  = (const float*)d_in[7];
    const float* W2r  = (const float*)d_in[8];
    const float* a2   = (const float*)d_in[9];
    const float* b2   = (const float*)d_in[10];
    const float* fc1w = (const float*)d_in[11];
    const float* fc1b = (const float*)d_in[12];
    const float* fc2w = (const float*)d_in[13];
    const float* fc2b = (const float*)d_in[14];
    const float* fcw  = (const float*)d_in[15];
    const float* fcb  = (const float*)d_in[16];
    float* out = (float*)d_out;

    int E = in_sizes[1] / 2;

    __half *xl1h, *xl2h, *h1;
    float *xr1, *xr2;
    cudaGetSymbolAddress((void**)&xl1h, g_xl1h);
    cudaGetSymbolAddress((void**)&xr1,  g_xr1);
    cudaGetSymbolAddress((void**)&h1,   g_h1);
    cudaGetSymbolAddress((void**)&xl2h, g_xl2h);
    cudaGetSymbolAddress((void**)&xr2,  g_xr2);

    const int GRID_M = (NN + 127) / 128;   // 235

    // CSR front half (independent of GEMM)
    k_init_deg<<<(NN + 255) / 256, 256>>>(NN);            // launch 0
    k_hist<<<(E + 255) / 256, 256>>>(ei, E);              // launch 1
    k_scan<<<1, 1024>>>(NN);                              // launch 2

    // layer 1 linear transforms (launch 3 -> ncu capture window)
    k_hgemm<float><<<dim3(2 * F1 / 64, GRID_M), 256>>>(x, W1l, W1r, xl1h, xr1,
                                                       NN, DIN, F1);

    // CSR back half
    k_csr_init<<<(NN + 255) / 256, 256>>>(NN);            // launch 4
    k_scatter<<<(E + 255) / 256, 256>>>(ei, E);           // launch 5

    // layer 1 attention + aggregation (+ELU fused, fp16 out)
    k_agg1<<<(NN * 32 + 255) / 256, 256>>>(a1, b1);       // launch 6

    // layer 2 linear transforms (A = fp16 h1)
    k_hgemm<__half><<<dim3(2 * F2 / 64, GRID_M), 256>>>(h1, W2l, W2r, xl2h, xr2,
                                                        NN, F1, F2);

    // layer 2 attention + aggregation (+bias)
    k_agg2<<<(NN * 32 + 255) / 256, 256>>>(a2, b2);

    // pool + MLP head
    k_pool<<<GG, 256>>>(bat, NN);
    k_mlp<<<1, 256>>>(fc1w, fc1b, fc2w, fc2b, fcw, fcb, out);
}

// round 12
// speedup vs baseline: 1.1520x; 1.0073x over previous
#include <cuda_runtime.h>
#include <cuda_fp16.h>
#include <math.h>
#include <stdint.h>

// ---------------- problem constants ----------------
#define NN     30000      // nodes
#define EMAX   480000     // edges (before self loops)
#define DIN    128
#define F1     256        // H1*DH
#define F2     64         // H2*DH
#define GG     64
#define DOUT   10
#define ETOT   (EMAX + NN)

// ---------------- scratch (device globals; no allocation allowed) ----------------
__device__ __half g_xh  [NN * DIN];       // fp16 input features
__device__ __half g_w1t [2 * F1 * DIN];   // fp16 [N=512][K=128]  (W1l|W1r)^T
__device__ __half g_w2t [2 * F2 * F1];    // fp16 [N=128][K=256]  (W2l|W2r)^T
__device__ __half g_xl1h[NN * F1];        // fp16 gathered operand, layer 1
__device__ float  g_xr1 [NN * F1];
__device__ __half g_h1  [NN * F1];        // fp16: only feeds GEMM2 A
__device__ __half g_xl2h[NN * F2];        // fp16 gathered operand, layer 2
__device__ float  g_xr2 [NN * F2];
__device__ float  g_h2  [NN * F2];
__device__ int    g_deg[NN];
__device__ int    g_row[NN + 1];
__device__ int    g_cur[NN];
__device__ int    g_csr[ETOT];
__device__ float  g_pool[GG * F2];

// ---------------- mma / cp.async helpers ----------------
__device__ __forceinline__ void mma_f16(float* d, const uint32_t* a, const uint32_t* b) {
    asm("mma.sync.aligned.m16n8k16.row.col.f32.f16.f16.f32 "
        "{%0,%1,%2,%3},{%4,%5,%6,%7},{%8,%9},{%0,%1,%2,%3};"
        : "+f"(d[0]), "+f"(d[1]), "+f"(d[2]), "+f"(d[3])
        : "r"(a[0]), "r"(a[1]), "r"(a[2]), "r"(a[3]), "r"(b[0]), "r"(b[1]));
}

__device__ __forceinline__ void cp16(void* smem, const void* gmem) {
    uint32_t s = (uint32_t)__cvta_generic_to_shared(smem);
    asm volatile("cp.async.cg.shared.global [%0], [%1], 16;" :: "r"(s), "l"(gmem));
}
#define CP_COMMIT()  asm volatile("cp.async.commit_group;")
#define CP_WAIT0()   asm volatile("cp.async.wait_group 0;")
#define CP_WAIT1()   asm volatile("cp.async.wait_group 1;")

// ---------------- fp16 cp.async double-buffered GEMM ----------------
// A [M,K] fp16 row-major; Bt [Nc,K] fp16 (N-major rows of K).
// C(:, 0:Nn) -> fp16 H0 ; C(:, Nn:Nc) -> fp32 C1.   Nc = 2*Nn.
// 256 thr, BM=128, BN=128, BK=32; warps 2x4; warp tile 64x32.
// smem rows padded to 20 uint32 (80B): conflict-free frag loads.
__global__ void __launch_bounds__(256) k_hgemm(const __half* __restrict__ A,
                                               const __half* __restrict__ Bt,
                                               __half* __restrict__ H0,
                                               float* __restrict__ C1,
                                               int M, int K, int Nn) {
    __shared__ uint32_t As[2][128][20];
    __shared__ uint32_t Bs[2][128][20];

    int n0 = blockIdx.x * 128;
    int m0 = blockIdx.y * 128;

    int tid  = threadIdx.x;
    int wid  = tid >> 5, lane = tid & 31;
    int g    = lane >> 2, t = lane & 3;
    int wm   = wid >> 2, wn = wid & 3;      // warp grid 2x4
    int wr   = wm * 64;
    int wc   = wn * 32;

    float acc[4][4][4];
#pragma unroll
    for (int i = 0; i < 4; i++)
#pragma unroll
        for (int j = 0; j < 4; j++)
#pragma unroll
            for (int q = 0; q < 4; q++) acc[i][j][q] = 0.f;

    // per-thread 2 chunks of 16B for A tile and 2 for B tile
    int c0   = tid * 2;
    int r_a  = c0 >> 2, o_a = c0 & 3;       // chunk0: row, 16B-offset
    int r_a1 = (c0 + 1) >> 2, o_a1 = (c0 + 1) & 3;
    int gr0 = m0 + r_a;  if (gr0 >= M) gr0 = M - 1;
    int gr1 = m0 + r_a1; if (gr1 >= M) gr1 = M - 1;

    const int nIter = K >> 5;

    // prologue: tile 0
    {
        cp16(&As[0][r_a ][o_a  * 4], A + (size_t)gr0 * K + o_a  * 8);
        cp16(&As[0][r_a1][o_a1 * 4], A + (size_t)gr1 * K + o_a1 * 8);
        cp16(&Bs[0][r_a ][o_a  * 4], Bt + (size_t)(n0 + r_a ) * K + o_a  * 8);
        cp16(&Bs[0][r_a1][o_a1 * 4], Bt + (size_t)(n0 + r_a1) * K + o_a1 * 8);
        CP_COMMIT();
    }

    for (int it = 0; it < nIter; it++) {
        int buf = it & 1;
        bool more = (it + 1) < nIter;
        if (more) {
            int k0 = (it + 1) << 5;
            int nb = buf ^ 1;
            cp16(&As[nb][r_a ][o_a  * 4], A + (size_t)gr0 * K + k0 + o_a  * 8);
            cp16(&As[nb][r_a1][o_a1 * 4], A + (size_t)gr1 * K + k0 + o_a1 * 8);
            cp16(&Bs[nb][r_a ][o_a  * 4], Bt + (size_t)(n0 + r_a ) * K + k0 + o_a  * 8);
            cp16(&Bs[nb][r_a1][o_a1 * 4], Bt + (size_t)(n0 + r_a1) * K + k0 + o_a1 * 8);
            CP_COMMIT();
            CP_WAIT1();
        } else {
            CP_WAIT0();
        }
        __syncthreads();

#pragma unroll
        for (int ks = 0; ks < 2; ks++) {
            int kk2 = ks * 8;                       // 8 uint32 = 16 halves per k-step
            uint32_t af[4][4], bf[4][2];
#pragma unroll
            for (int mt = 0; mt < 4; mt++) {
                int r = wr + mt * 16 + g;
                af[mt][0] = As[buf][r][kk2 + t];
                af[mt][1] = As[buf][r + 8][kk2 + t];
                af[mt][2] = As[buf][r][kk2 + t + 4];
                af[mt][3] = As[buf][r + 8][kk2 + t + 4];
            }
#pragma unroll
            for (int nt = 0; nt < 4; nt++) {
                int n = wc + nt * 8 + g;
                bf[nt][0] = Bs[buf][n][kk2 + t];
                bf[nt][1] = Bs[buf][n][kk2 + t + 4];
            }
#pragma unroll
            for (int mt = 0; mt < 4; mt++)
#pragma unroll
                for (int nt = 0; nt < 4; nt++)
                    mma_f16(acc[mt][nt], af[mt], bf[nt]);
        }
        __syncthreads();
    }

    // epilogue: columns < Nn -> fp16 H0, else -> fp32 C1
#pragma unroll
    for (int mt = 0; mt < 4; mt++) {
        int r0 = m0 + wr + mt * 16 + g;
        int r1 = r0 + 8;
#pragma unroll
        for (int nt = 0; nt < 4; nt++) {
            int cc = n0 + wc + nt * 8 + t * 2;
            if (cc < Nn) {
                __half2 h01 = __floats2half2_rn(acc[mt][nt][0], acc[mt][nt][1]);
                __half2 h23 = __floats2half2_rn(acc[mt][nt][2], acc[mt][nt][3]);
                if (r0 < M) *(__half2*)(H0 + (size_t)r0 * Nn + cc) = h01;
                if (r1 < M) *(__half2*)(H0 + (size_t)r1 * Nn + cc) = h23;
            } else {
                int c2 = cc - Nn;
                if (r0 < M)
                    *(float2*)(C1 + (size_t)r0 * Nn + c2) = make_float2(acc[mt][nt][0], acc[mt][nt][1]);
                if (r1 < M)
                    *(float2*)(C1 + (size_t)r1 * Nn + c2) = make_float2(acc[mt][nt][2], acc[mt][nt][3]);
            }
        }
    }
}

// ---------------- fp16 conversions ----------------
__global__ void k_cvt_x(const float* __restrict__ x) {
    int i = blockIdx.x * blockDim.x + threadIdx.x;   // one per 8 elems
    if (i >= NN * DIN / 8) return;
    float4 v0 = *(const float4*)(x + (size_t)i * 8);
    float4 v1 = *(const float4*)(x + (size_t)i * 8 + 4);
    __half2 h0 = __floats2half2_rn(v0.x, v0.y);
    __half2 h1 = __floats2half2_rn(v0.z, v0.w);
    __half2 h2 = __floats2half2_rn(v1.x, v1.y);
    __half2 h3 = __floats2half2_rn(v1.z, v1.w);
    uint4 u = make_uint4(*(uint32_t*)&h0, *(uint32_t*)&h1,
                         *(uint32_t*)&h2, *(uint32_t*)&h3);
    *(uint4*)(g_xh + (size_t)i * 8) = u;
}

// weights -> fp16, transposed to [N][K] concat layouts
__global__ void k_cvt_w(const float* __restrict__ W1l, const float* __restrict__ W1r,
                        const float* __restrict__ W2l, const float* __restrict__ W2r) {
    int i = blockIdx.x * blockDim.x + threadIdx.x;
    const int SZ1 = 2 * F1 * DIN;          // 65536
    const int SZ2 = 2 * F2 * F1;           // 32768
    if (i < SZ1) {
        int n = i / DIN, k = i - n * DIN;
        float v = (n < F1) ? W1l[(size_t)k * F1 + n] : W1r[(size_t)k * F1 + (n - F1)];
        g_w1t[i] = __float2half_rn(v);
    } else if (i < SZ1 + SZ2) {
        int j = i - SZ1;
        int n = j / F1, k = j - n * F1;
        float v = (n < F2) ? W2l[(size_t)k * F2 + n] : W2r[(size_t)k * F2 + (n - F2)];
        g_w2t[j] = __float2half_rn(v);
    }
}

// ---------------- CSR build ----------------
__global__ void k_hist(const int* __restrict__ ei, int E) {
    int e = blockIdx.x * blockDim.x + threadIdx.x;
    if (e < E) atomicAdd(&g_deg[ei[E + e]], 1);
}

// 1024-thread shuffle scan (+1 self loop folded in) fused with csr_init
__global__ void k_scan(int n) {
    __shared__ int wsum[32];
    __shared__ int carry;
    int tid = threadIdx.x, lane = tid & 31, wid = tid >> 5;
    if (tid == 0) carry = 0;
    __syncthreads();
    for (int base = 0; base < n; base += 1024) {
        int i = base + tid;
        int v = (i < n) ? (g_deg[i] + 1) : 0;     // +1 = self loop
        int incl = v;
#pragma unroll
        for (int off = 1; off < 32; off <<= 1) {
            int tt = __shfl_up_sync(0xffffffffu, incl, off);
            if (lane >= off) incl += tt;
        }
        if (lane == 31) wsum[wid] = incl;
        __syncthreads();
        if (wid == 0) {
            int s = wsum[lane];
#pragma unroll
            for (int off = 1; off < 32; off <<= 1) {
                int tt = __shfl_up_sync(0xffffffffu, s, off);
                if (lane >= off) s += tt;
            }
            wsum[lane] = s;
        }
        __syncthreads();
        int woff = wid ? wsum[wid - 1] : 0;
        int c = carry;
        if (i < n) {
            int r = c + woff + incl - v;          // exclusive
            g_row[i] = r;
            g_csr[r] = i;                          // self loop first
            g_cur[i] = r + 1;
        }
        __syncthreads();
        if (tid == 0) carry = c + wsum[31];
        __syncthreads();
    }
    if (tid == 0) g_row[n] = carry;
}

__global__ void k_scatter(const int* __restrict__ ei, int E) {
    int e = blockIdx.x * blockDim.x + threadIdx.x;
    if (e < E) {
        int dst = ei[E + e];
        int pos = atomicAdd(&g_cur[dst], 1);
        g_csr[pos] = ei[e];
    }
}

// ---------------- GATv2 aggregation, layer 1 (fp16 gather, fp16 h1 out) ------
__global__ void k_agg1(const float* __restrict__ att, const float* __restrict__ bias) {
    int warp = (blockIdx.x * blockDim.x + threadIdx.x) >> 5;
    if (warp >= NN) return;
    int lane = threadIdx.x & 31;
    int base = (lane >> 2) * 32 + (lane & 3) * 8;

    float xr[8], av[8];
    {
        float4 r0 = *(const float4*)(g_xr1 + (size_t)warp * F1 + base);
        float4 r1 = *(const float4*)(g_xr1 + (size_t)warp * F1 + base + 4);
        xr[0]=r0.x; xr[1]=r0.y; xr[2]=r0.z; xr[3]=r0.w;
        xr[4]=r1.x; xr[5]=r1.y; xr[6]=r1.z; xr[7]=r1.w;
        float4 a0 = *(const float4*)(att + base);
        float4 a1 = *(const float4*)(att + base + 4);
        av[0]=a0.x; av[1]=a0.y; av[2]=a0.z; av[3]=a0.w;
        av[4]=a1.x; av[5]=a1.y; av[6]=a1.z; av[7]=a1.w;
    }

    float acc[8];
#pragma unroll
    for (int j = 0; j < 8; j++) acc[j] = 0.f;
    float m = -3.0e38f, z = 0.f;

    const __half* xb = g_xl1h + base;
    int e0 = g_row[warp], e1 = g_row[warp + 1];
    uint4 nu = *(const uint4*)(xb + (size_t)g_csr[e0] * F1);
    for (int e = e0; e < e1; e++) {
        uint4 u = nu;
        if (e + 1 < e1)
            nu = *(const uint4*)(xb + (size_t)g_csr[e + 1] * F1);
        __half2* hh = (__half2*)&u;
        float2 p0 = __half22float2(hh[0]);
        float2 p1 = __half22float2(hh[1]);
        float2 p2 = __half22float2(hh[2]);
        float2 p3 = __half22float2(hh[3]);
        float xj[8] = {p0.x, p0.y, p1.x, p1.y, p2.x, p2.y, p3.x, p3.y};
        float t = 0.f;
#pragma unroll
        for (int j = 0; j < 8; j++) {
            float v = xj[j] + xr[j];
            v = (v > 0.f) ? v : 0.2f * v;
            t = fmaf(v, av[j], t);
        }
        t += __shfl_xor_sync(0xffffffffu, t, 1);
        t += __shfl_xor_sync(0xffffffffu, t, 2);
        float mn = fmaxf(m, t);
        float sc = __expf(m - mn);
        float w  = __expf(t - mn);
        z = z * sc + w;
#pragma unroll
        for (int j = 0; j < 8; j++)
            acc[j] = fmaf(acc[j], sc, w * xj[j]);
        m = mn;
    }
    float inv = 1.f / z;
    float o[8];
#pragma unroll
    for (int j = 0; j < 8; j++) {
        float v = acc[j] * inv + bias[base + j];
        o[j] = (v > 0.f) ? v : expm1f(v);          // ELU fused
    }
    __half2 h0 = __floats2half2_rn(o[0], o[1]);
    __half2 h1 = __floats2half2_rn(o[2], o[3]);
    __half2 h2 = __floats2half2_rn(o[4], o[5]);
    __half2 h3 = __floats2half2_rn(o[6], o[7]);
    uint4 uo = make_uint4(*(uint32_t*)&h0, *(uint32_t*)&h1,
                          *(uint32_t*)&h2, *(uint32_t*)&h3);
    *(uint4*)(g_h1 + (size_t)warp * F1 + base) = uo;
}

// ---------------- GATv2 aggregation, layer 2 (fp16 gather) -------------------
__global__ void k_agg2(const float* __restrict__ att, const float* __restrict__ bias) {
    int warp = (blockIdx.x * blockDim.x + threadIdx.x) >> 5;
    if (warp >= NN) return;
    int lane = threadIdx.x & 31;
    int base = (lane >> 4) * 32 + (lane & 15) * 2;

    float2 xr = *(const float2*)(g_xr2 + (size_t)warp * F2 + base);
    float2 av = *(const float2*)(att + base);

    float acc0 = 0.f, acc1 = 0.f;
    float m = -3.0e38f, z = 0.f;

    const __half* xb = g_xl2h + base;
    int e0 = g_row[warp], e1 = g_row[warp + 1];
    __half2 nx = *(const __half2*)(xb + (size_t)g_csr[e0] * F2);
    for (int e = e0; e < e1; e++) {
        float2 xj = __half22float2(nx);
        if (e + 1 < e1)
            nx = *(const __half2*)(xb + (size_t)g_csr[e + 1] * F2);
        float v0 = xj.x + xr.x; v0 = (v0 > 0.f) ? v0 : 0.2f * v0;
        float v1 = xj.y + xr.y; v1 = (v1 > 0.f) ? v1 : 0.2f * v1;
        float t = fmaf(v0, av.x, v1 * av.y);
        t += __shfl_xor_sync(0xffffffffu, t, 1);
        t += __shfl_xor_sync(0xffffffffu, t, 2);
        t += __shfl_xor_sync(0xffffffffu, t, 4);
        t += __shfl_xor_sync(0xffffffffu, t, 8);
        float mn = fmaxf(m, t);
        float sc = __expf(m - mn);
        float w  = __expf(t - mn);
        z = z * sc + w;
        acc0 = fmaf(acc0, sc, w * xj.x);
        acc1 = fmaf(acc1, sc, w * xj.y);
        m = mn;
    }
    float inv = 1.f / z;
    g_h2[(size_t)warp * F2 + base + 0] = acc0 * inv + bias[base + 0];
    g_h2[(size_t)warp * F2 + base + 1] = acc1 * inv + bias[base + 1];
}

// ---------------- mean pool over sorted batch ----------------
__device__ __forceinline__ int lb(const int* b, int n, int g) {
    int lo = 0, hi = n;
    while (lo < hi) { int mid = (lo + hi) >> 1; if (b[mid] < g) lo = mid + 1; else hi = mid; }
    return lo;
}

__global__ void k_pool(const int* __restrict__ batch, int n) {
    __shared__ float part[4][64];
    int g = blockIdx.x;
    int d = threadIdx.x & 63;
    int ty = threadIdx.x >> 6;
    int s = lb(batch, n, g);
    int e = lb(batch, n, g + 1);
    float sum = 0.f;
    for (int i = s + ty; i < e; i += 4) sum += g_h2[(size_t)i * F2 + d];
    part[ty][d] = sum;
    __syncthreads();
    if (ty == 0) {
        float tot = part[0][d] + part[1][d] + part[2][d] + part[3][d];
        int cnt = e - s; if (cnt < 1) cnt = 1;
        g_pool[g * F2 + d] = tot / (float)cnt;
    }
}

// ---------------- MLP head ----------------
__global__ void k_mlp(const float* __restrict__ fc1w, const float* __restrict__ fc1b,
                      const float* __restrict__ fc2w, const float* __restrict__ fc2b,
                      const float* __restrict__ fcw,  const float* __restrict__ fcb,
                      float* __restrict__ out) {
    __shared__ float hg[GG * 64];
    __shared__ float x1[GG * 32];
    __shared__ float x2[GG * 16];
    int tid = threadIdx.x;
    for (int i = tid; i < GG * 64; i += 256) hg[i] = g_pool[i];
    __syncthreads();
    for (int i = tid; i < GG * 32; i += 256) {
        int g = i >> 5, o = i & 31;
        float s = fc1b[o];
        for (int k = 0; k < 64; k++) s = fmaf(hg[g * 64 + k], fc1w[k * 32 + o], s);
        x1[i] = fmaxf(s, 0.f);
    }
    __syncthreads();
    for (int i = tid; i < GG * 16; i += 256) {
        int g = i >> 4, o = i & 15;
        float s = fc2b[o];
        for (int k = 0; k < 32; k++) s = fmaf(x1[g * 32 + k], fc2w[k * 16 + o], s);
        float v = fmaxf(s, 0.f);
        x2[i] = v;
        out[GG * DOUT + i] = v;
    }
    __syncthreads();
    for (int i = tid; i < GG * DOUT; i += 256) {
        int g = i / DOUT, o = i - g * DOUT;
        float s = fcb[o];
        for (int k = 0; k < 16; k++) s = fmaf(x2[g * 16 + k], fcw[k * DOUT + o], s);
        out[i] = s;
    }
}

// ---------------- launch ----------------
extern "C" void kernel_launch(void* const* d_in, const int* in_sizes, int n_in,
                              void* d_out, int out_size) {
    const float* x    = (const float*)d_in[0];
    const int*   ei   = (const int*)  d_in[1];
    const int*   bat  = (const int*)  d_in[2];
    const float* W1l  = (const float*)d_in[3];
    const float* W1r  = (const float*)d_in[4];
    const float* a1   = (const float*)d_in[5];
    const float* b1   = (const float*)d_in[6];
    const float* W2l  = (const float*)d_in[7];
    const float* W2r  = (const float*)d_in[8];
    const float* a2   = (const float*)d_in[9];
    const float* b2   = (const float*)d_in[10];
    const float* fc1w = (const float*)d_in[11];
    const float* fc1b = (const float*)d_in[12];
    const float* fc2w = (const float*)d_in[13];
    const float* fc2b = (const float*)d_in[14];
    const float* fcw  = (const float*)d_in[15];
    const float* fcb  = (const float*)d_in[16];
    float* out = (float*)d_out;

    int E = in_sizes[1] / 2;

    __half *xh, *w1t, *w2t, *xl1h, *xl2h, *h1;
    float *xr1, *xr2;
    int *deg;
    cudaGetSymbolAddress((void**)&xh,   g_xh);
    cudaGetSymbolAddress((void**)&w1t,  g_w1t);
    cudaGetSymbolAddress((void**)&w2t,  g_w2t);
    cudaGetSymbolAddress((void**)&xl1h, g_xl1h);
    cudaGetSymbolAddress((void**)&xr1,  g_xr1);
    cudaGetSymbolAddress((void**)&h1,   g_h1);
    cudaGetSymbolAddress((void**)&xl2h, g_xl2h);
    cudaGetSymbolAddress((void**)&xr2,  g_xr2);
    cudaGetSymbolAddress((void**)&deg,  g_deg);

    const int GRID_M = (NN + 127) / 128;   // 235

    cudaMemsetAsync(deg, 0, NN * sizeof(int));            // memset node

    // conversions + CSR front
    k_cvt_x<<<(NN * DIN / 8 + 255) / 256, 256>>>(x);      // launch 0
    k_cvt_w<<<(2 * F1 * DIN + 2 * F2 * F1 + 255) / 256, 256>>>(W1l, W1r, W2l, W2r); // 1
    k_hist<<<(E + 255) / 256, 256>>>(ei, E);              // launch 2

    // layer 1 linear transforms (launch 3 -> ncu capture window)
    k_hgemm<<<dim3(2 * F1 / 128, GRID_M), 256>>>(xh, w1t, xl1h, xr1, NN, DIN, F1);

    k_scan<<<1, 1024>>>(NN);                              // launch 4 (fused csr_init)
    k_scatter<<<(E + 255) / 256, 256>>>(ei, E);           // launch 5

    // layer 1 attention + aggregation (+ELU fused, fp16 out)
    k_agg1<<<(NN * 32 + 255) / 256, 256>>>(a1, b1);       // launch 6

    // layer 2 linear transforms (A = fp16 h1)
    k_hgemm<<<dim3(2 * F2 / 128, GRID_M), 256>>>(h1, w2t, xl2h, xr2, NN, F1, F2);

    // layer 2 attention + aggregation (+bias)
    k_agg2<<<(NN * 32 + 255) / 256, 256>>>(a2, b2);

    // pool + MLP head
    k_pool<<<GG, 256>>>(bat, NN);
    k_mlp<<<1, 256>>>(fc1w, fc1b, fc2w, fc2b, fcw, fcb, out);
}

// round 13
// speedup vs baseline: 1.2242x; 1.0626x over previous
#include <cuda_runtime.h>
#include <cuda_fp16.h>
#include <math.h>
#include <stdint.h>

// ---------------- problem constants ----------------
#define NN     30000      // nodes
#define EMAX   480000     // edges (before self loops)
#define DIN    128
#define F1     256        // H1*DH
#define F2     64         // H2*DH
#define GG     64
#define DOUT   10
#define ETOT   (EMAX + NN)

// ---------------- scratch (device globals; no allocation allowed) ----------------
__device__ __half g_xh  [NN * DIN];       // fp16 input features
__device__ __half g_w1t [2 * F1 * DIN];   // fp16 [N=512][K=128]  (W1l|W1r)^T
__device__ __half g_w2t [2 * F2 * F1];    // fp16 [N=128][K=256]  (W2l|W2r)^T
__device__ __half g_xl1h[NN * F1];        // fp16 gathered operand, layer 1
__device__ float  g_xr1 [NN * F1];
__device__ __half g_h1  [NN * F1];        // fp16: only feeds GEMM2 A
__device__ __half g_xl2h[NN * F2];        // fp16 gathered operand, layer 2
__device__ float  g_xr2 [NN * F2];
__device__ float  g_h2  [NN * F2];
__device__ int    g_deg[NN];
__device__ int    g_row[NN + 1];
__device__ int    g_cur[NN];
__device__ int    g_csr[ETOT];
__device__ float  g_pool[GG * F2];

// ---------------- mma / cp.async / ldmatrix helpers ----------------
__device__ __forceinline__ void mma_f16(float* d, const uint32_t* a, const uint32_t* b) {
    asm("mma.sync.aligned.m16n8k16.row.col.f32.f16.f16.f32 "
        "{%0,%1,%2,%3},{%4,%5,%6,%7},{%8,%9},{%0,%1,%2,%3};"
        : "+f"(d[0]), "+f"(d[1]), "+f"(d[2]), "+f"(d[3])
        : "r"(a[0]), "r"(a[1]), "r"(a[2]), "r"(a[3]), "r"(b[0]), "r"(b[1]));
}

__device__ __forceinline__ void cp16(void* smem, const void* gmem) {
    uint32_t s = (uint32_t)__cvta_generic_to_shared(smem);
    asm volatile("cp.async.cg.shared.global [%0], [%1], 16;" :: "r"(s), "l"(gmem));
}
#define CP_COMMIT()  asm volatile("cp.async.commit_group;")
#define CP_WAIT0()   asm volatile("cp.async.wait_group 0;")
#define CP_WAIT1()   asm volatile("cp.async.wait_group 1;")

__device__ __forceinline__ void ldsm4(uint32_t* r, uint32_t saddr) {
    asm volatile("ldmatrix.sync.aligned.m8n8.x4.shared.b16 {%0,%1,%2,%3}, [%4];"
        : "=r"(r[0]), "=r"(r[1]), "=r"(r[2]), "=r"(r[3]) : "r"(saddr));
}

// ---------------- fp16 cp.async + ldmatrix double-buffered GEMM --------------
// A [M,K] fp16 row-major; Bt [Nc,K] fp16 (N-major rows of K).
// C(:, 0:Nn) -> fp16 H0 ; C(:, Nn:Nc) -> fp32 C1.   Nc = 2*Nn.
// 256 thr, BM=128, BN=128, BK=32; warps 2x4; warp tile 64x32.
// smem rows = 20 uint32 (80B): ldmatrix 8-row phases are bank-conflict-free.
__global__ void __launch_bounds__(256) k_hgemm(const __half* __restrict__ A,
                                               const __half* __restrict__ Bt,
                                               __half* __restrict__ H0,
                                               float* __restrict__ C1,
                                               int M, int K, int Nn) {
    __shared__ uint32_t As[2][128][20];
    __shared__ uint32_t Bs[2][128][20];

    int n0 = blockIdx.x * 128;
    int m0 = blockIdx.y * 128;

    int tid  = threadIdx.x;
    int wid  = tid >> 5, lane = tid & 31;
    int g    = lane >> 2, t = lane & 3;
    int wm   = wid >> 2, wn = wid & 3;      // warp grid 2x4
    int wr   = wm * 64;
    int wc   = wn * 32;

    float acc[4][4][4];
#pragma unroll
    for (int i = 0; i < 4; i++)
#pragma unroll
        for (int j = 0; j < 4; j++)
#pragma unroll
            for (int q = 0; q < 4; q++) acc[i][j][q] = 0.f;

    // per-thread 2 chunks of 16B for A tile and 2 for B tile
    int c0   = tid * 2;
    int r_a  = c0 >> 2, o_a = c0 & 3;       // chunk0: row, 16B-offset
    int r_a1 = (c0 + 1) >> 2, o_a1 = (c0 + 1) & 3;
    int gr0 = m0 + r_a;  if (gr0 >= M) gr0 = M - 1;
    int gr1 = m0 + r_a1; if (gr1 >= M) gr1 = M - 1;

    // ldmatrix per-lane byte offsets (within a buffer)
    uint32_t sA0 = (uint32_t)__cvta_generic_to_shared(&As[0][0][0]);
    uint32_t sB0 = (uint32_t)__cvta_generic_to_shared(&Bs[0][0][0]);
    uint32_t aoff = (uint32_t)(wr + (lane & 15)) * 80u + (uint32_t)(lane >> 4) * 16u;
    uint32_t boff = (uint32_t)(wc + (lane & 7) + ((lane >> 4) << 3)) * 80u
                  + (uint32_t)((lane >> 3) & 1) * 16u;

    const int nIter = K >> 5;

    // prologue: tile 0
    {
        cp16(&As[0][r_a ][o_a  * 4], A + (size_t)gr0 * K + o_a  * 8);
        cp16(&As[0][r_a1][o_a1 * 4], A + (size_t)gr1 * K + o_a1 * 8);
        cp16(&Bs[0][r_a ][o_a  * 4], Bt + (size_t)(n0 + r_a ) * K + o_a  * 8);
        cp16(&Bs[0][r_a1][o_a1 * 4], Bt + (size_t)(n0 + r_a1) * K + o_a1 * 8);
        CP_COMMIT();
    }

    for (int it = 0; it < nIter; it++) {
        int buf = it & 1;
        bool more = (it + 1) < nIter;
        if (more) {
            int k0 = (it + 1) << 5;
            int nb = buf ^ 1;
            cp16(&As[nb][r_a ][o_a  * 4], A + (size_t)gr0 * K + k0 + o_a  * 8);
            cp16(&As[nb][r_a1][o_a1 * 4], A + (size_t)gr1 * K + k0 + o_a1 * 8);
            cp16(&Bs[nb][r_a ][o_a  * 4], Bt + (size_t)(n0 + r_a ) * K + k0 + o_a  * 8);
            cp16(&Bs[nb][r_a1][o_a1 * 4], Bt + (size_t)(n0 + r_a1) * K + k0 + o_a1 * 8);
            CP_COMMIT();
            CP_WAIT1();
        } else {
            CP_WAIT0();
        }
        __syncthreads();

        uint32_t bufA = sA0 + (uint32_t)buf * 10240u;
        uint32_t bufB = sB0 + (uint32_t)buf * 10240u;
#pragma unroll
        for (int ks = 0; ks < 2; ks++) {
            uint32_t kb = (uint32_t)ks * 32u;        // 8 uint32 = 32 bytes per k-step
            uint32_t af[4][4], bfr[2][4];
#pragma unroll
            for (int mt = 0; mt < 4; mt++)
                ldsm4(af[mt], bufA + (uint32_t)(mt * 16) * 80u + kb + aoff);
#pragma unroll
            for (int p = 0; p < 2; p++)
                ldsm4(bfr[p], bufB + (uint32_t)(p * 16) * 80u + kb + boff);
#pragma unroll
            for (int mt = 0; mt < 4; mt++)
#pragma unroll
                for (int nt = 0; nt < 4; nt++)
                    mma_f16(acc[mt][nt], af[mt], &bfr[nt >> 1][(nt & 1) * 2]);
        }
        __syncthreads();
    }

    // epilogue: columns < Nn -> fp16 H0, else -> fp32 C1
#pragma unroll
    for (int mt = 0; mt < 4; mt++) {
        int r0 = m0 + wr + mt * 16 + g;
        int r1 = r0 + 8;
#pragma unroll
        for (int nt = 0; nt < 4; nt++) {
            int cc = n0 + wc + nt * 8 + t * 2;
            if (cc < Nn) {
                __half2 h01 = __floats2half2_rn(acc[mt][nt][0], acc[mt][nt][1]);
                __half2 h23 = __floats2half2_rn(acc[mt][nt][2], acc[mt][nt][3]);
                if (r0 < M) *(__half2*)(H0 + (size_t)r0 * Nn + cc) = h01;
                if (r1 < M) *(__half2*)(H0 + (size_t)r1 * Nn + cc) = h23;
            } else {
                int c2 = cc - Nn;
                if (r0 < M)
                    *(float2*)(C1 + (size_t)r0 * Nn + c2) = make_float2(acc[mt][nt][0], acc[mt][nt][1]);
                if (r1 < M)
                    *(float2*)(C1 + (size_t)r1 * Nn + c2) = make_float2(acc[mt][nt][2], acc[mt][nt][3]);
            }
        }
    }
}

// ---------------- fused prep: x->fp16, weights->fp16 transposed, degree hist --
__global__ void k_prep(const float* __restrict__ x,
                       const float* __restrict__ W1l, const float* __restrict__ W1r,
                       const float* __restrict__ W2l, const float* __restrict__ W2r,
                       const int* __restrict__ ei, int E) {
    const int NX  = NN * DIN / 8;          // 480000 (8 elems per thread)
    const int SZ1 = 2 * F1 * DIN;          // 65536
    const int SZ2 = 2 * F2 * F1;           // 32768
    int i = blockIdx.x * blockDim.x + threadIdx.x;
    if (i < NX) {
        float4 v0 = *(const float4*)(x + (size_t)i * 8);
        float4 v1 = *(const float4*)(x + (size_t)i * 8 + 4);
        __half2 h0 = __floats2half2_rn(v0.x, v0.y);
        __half2 h1 = __floats2half2_rn(v0.z, v0.w);
        __half2 h2 = __floats2half2_rn(v1.x, v1.y);
        __half2 h3 = __floats2half2_rn(v1.z, v1.w);
        uint4 u = make_uint4(*(uint32_t*)&h0, *(uint32_t*)&h1,
                             *(uint32_t*)&h2, *(uint32_t*)&h3);
        *(uint4*)(g_xh + (size_t)i * 8) = u;
    } else if (i < NX + SZ1) {
        int j = i - NX;
        int n = j / DIN, k = j - n * DIN;
        float v = (n < F1) ? W1l[(size_t)k * F1 + n] : W1r[(size_t)k * F1 + (n - F1)];
        g_w1t[j] = __float2half_rn(v);
    } else if (i < NX + SZ1 + SZ2) {
        int j = i - NX - SZ1;
        int n = j / F1, k = j - n * F1;
        float v = (n < F2) ? W2l[(size_t)k * F2 + n] : W2r[(size_t)k * F2 + (n - F2)];
        g_w2t[j] = __float2half_rn(v);
    } else if (i < NX + SZ1 + SZ2 + E) {
        int e = i - NX - SZ1 - SZ2;
        atomicAdd(&g_deg[ei[E + e]], 1);
    }
}

// ---------------- CSR build ----------------
// 1024-thread shuffle scan (+1 self loop folded in) fused with csr_init
__global__ void k_scan(int n) {
    __shared__ int wsum[32];
    __shared__ int carry;
    int tid = threadIdx.x, lane = tid & 31, wid = tid >> 5;
    if (tid == 0) carry = 0;
    __syncthreads();
    for (int base = 0; base < n; base += 1024) {
        int i = base + tid;
        int v = (i < n) ? (g_deg[i] + 1) : 0;     // +1 = self loop
        int incl = v;
#pragma unroll
        for (int off = 1; off < 32; off <<= 1) {
            int tt = __shfl_up_sync(0xffffffffu, incl, off);
            if (lane >= off) incl += tt;
        }
        if (lane == 31) wsum[wid] = incl;
        __syncthreads();
        if (wid == 0) {
            int s = wsum[lane];
#pragma unroll
            for (int off = 1; off < 32; off <<= 1) {
                int tt = __shfl_up_sync(0xffffffffu, s, off);
                if (lane >= off) s += tt;
            }
            wsum[lane] = s;
        }
        __syncthreads();
        int woff = wid ? wsum[wid - 1] : 0;
        int c = carry;
        if (i < n) {
            int r = c + woff + incl - v;          // exclusive
            g_row[i] = r;
            g_csr[r] = i;                          // self loop first
            g_cur[i] = r + 1;
        }
        __syncthreads();
        if (tid == 0) carry = c + wsum[31];
        __syncthreads();
    }
    if (tid == 0) g_row[n] = carry;
}

__global__ void k_scatter(const int* __restrict__ ei, int E) {
    int e = blockIdx.x * blockDim.x + threadIdx.x;
    if (e < E) {
        int dst = ei[E + e];
        int pos = atomicAdd(&g_cur[dst], 1);
        g_csr[pos] = ei[e];
    }
}

// ---------------- GATv2 aggregation, layer 1 (no-max softmax; fp16 I/O) ------
// Softmax is shift-invariant; scores are bounded (|e| <~ 10), so exp() is safe.
__global__ void k_agg1(const float* __restrict__ att, const float* __restrict__ bias) {
    int warp = (blockIdx.x * blockDim.x + threadIdx.x) >> 5;
    if (warp >= NN) return;
    int lane = threadIdx.x & 31;
    int base = (lane >> 2) * 32 + (lane & 3) * 8;

    float xr[8], av[8];
    {
        float4 r0 = *(const float4*)(g_xr1 + (size_t)warp * F1 + base);
        float4 r1 = *(const float4*)(g_xr1 + (size_t)warp * F1 + base + 4);
        xr[0]=r0.x; xr[1]=r0.y; xr[2]=r0.z; xr[3]=r0.w;
        xr[4]=r1.x; xr[5]=r1.y; xr[6]=r1.z; xr[7]=r1.w;
        float4 a0 = *(const float4*)(att + base);
        float4 a1 = *(const float4*)(att + base + 4);
        av[0]=a0.x; av[1]=a0.y; av[2]=a0.z; av[3]=a0.w;
        av[4]=a1.x; av[5]=a1.y; av[6]=a1.z; av[7]=a1.w;
    }

    float acc[8];
#pragma unroll
    for (int j = 0; j < 8; j++) acc[j] = 0.f;
    float z = 0.f;

    const __half* xb = g_xl1h + base;
    int e0 = g_row[warp], e1 = g_row[warp + 1];
    uint4 nu = *(const uint4*)(xb + (size_t)g_csr[e0] * F1);
    for (int e = e0; e < e1; e++) {
        uint4 u = nu;
        if (e + 1 < e1)
            nu = *(const uint4*)(xb + (size_t)g_csr[e + 1] * F1);
        __half2* hh = (__half2*)&u;
        float2 p0 = __half22float2(hh[0]);
        float2 p1 = __half22float2(hh[1]);
        float2 p2 = __half22float2(hh[2]);
        float2 p3 = __half22float2(hh[3]);
        float xj[8] = {p0.x, p0.y, p1.x, p1.y, p2.x, p2.y, p3.x, p3.y};
        float t = 0.f;
#pragma unroll
        for (int j = 0; j < 8; j++) {
            float v = xj[j] + xr[j];
            v = (v > 0.f) ? v : 0.2f * v;
            t = fmaf(v, av[j], t);
        }
        t += __shfl_xor_sync(0xffffffffu, t, 1);
        t += __shfl_xor_sync(0xffffffffu, t, 2);
        float w = __expf(t);
        z += w;
#pragma unroll
        for (int j = 0; j < 8; j++)
            acc[j] = fmaf(w, xj[j], acc[j]);
    }
    float inv = 1.f / z;
    float o[8];
#pragma unroll
    for (int j = 0; j < 8; j++) {
        float v = acc[j] * inv + bias[base + j];
        o[j] = (v > 0.f) ? v : expm1f(v);          // ELU fused
    }
    __half2 h0 = __floats2half2_rn(o[0], o[1]);
    __half2 h1 = __floats2half2_rn(o[2], o[3]);
    __half2 h2 = __floats2half2_rn(o[4], o[5]);
    __half2 h3 = __floats2half2_rn(o[6], o[7]);
    uint4 uo = make_uint4(*(uint32_t*)&h0, *(uint32_t*)&h1,
                          *(uint32_t*)&h2, *(uint32_t*)&h3);
    *(uint4*)(g_h1 + (size_t)warp * F1 + base) = uo;
}

// ---------------- GATv2 aggregation, layer 2 (no-max softmax; fp16 gather) ---
__global__ void k_agg2(const float* __restrict__ att, const float* __restrict__ bias) {
    int warp = (blockIdx.x * blockDim.x + threadIdx.x) >> 5;
    if (warp >= NN) return;
    int lane = threadIdx.x & 31;
    int base = (lane >> 4) * 32 + (lane & 15) * 2;

    float2 xr = *(const float2*)(g_xr2 + (size_t)warp * F2 + base);
    float2 av = *(const float2*)(att + base);

    float acc0 = 0.f, acc1 = 0.f, z = 0.f;

    const __half* xb = g_xl2h + base;
    int e0 = g_row[warp], e1 = g_row[warp + 1];
    __half2 nx = *(const __half2*)(xb + (size_t)g_csr[e0] * F2);
    for (int e = e0; e < e1; e++) {
        float2 xj = __half22float2(nx);
        if (e + 1 < e1)
            nx = *(const __half2*)(xb + (size_t)g_csr[e + 1] * F2);
        float v0 = xj.x + xr.x; v0 = (v0 > 0.f) ? v0 : 0.2f * v0;
        float v1 = xj.y + xr.y; v1 = (v1 > 0.f) ? v1 : 0.2f * v1;
        float t = fmaf(v0, av.x, v1 * av.y);
        t += __shfl_xor_sync(0xffffffffu, t, 1);
        t += __shfl_xor_sync(0xffffffffu, t, 2);
        t += __shfl_xor_sync(0xffffffffu, t, 4);
        t += __shfl_xor_sync(0xffffffffu, t, 8);
        float w = __expf(t);
        z += w;
        acc0 = fmaf(w, xj.x, acc0);
        acc1 = fmaf(w, xj.y, acc1);
    }
    float inv = 1.f / z;
    g_h2[(size_t)warp * F2 + base + 0] = acc0 * inv + bias[base + 0];
    g_h2[(size_t)warp * F2 + base + 1] = acc1 * inv + bias[base + 1];
}

// ---------------- mean pool over sorted batch ----------------
__device__ __forceinline__ int lb(const int* b, int n, int g) {
    int lo = 0, hi = n;
    while (lo < hi) { int mid = (lo + hi) >> 1; if (b[mid] < g) lo = mid + 1; else hi = mid; }
    return lo;
}

__global__ void k_pool(const int* __restrict__ batch, int n) {
    __shared__ float part[4][64];
    int g = blockIdx.x;
    int d = threadIdx.x & 63;
    int ty = threadIdx.x >> 6;
    int s = lb(batch, n, g);
    int e = lb(batch, n, g + 1);
    float sum = 0.f;
    for (int i = s + ty; i < e; i += 4) sum += g_h2[(size_t)i * F2 + d];
    part[ty][d] = sum;
    __syncthreads();
    if (ty == 0) {
        float tot = part[0][d] + part[1][d] + part[2][d] + part[3][d];
        int cnt = e - s; if (cnt < 1) cnt = 1;
        g_pool[g * F2 + d] = tot / (float)cnt;
    }
}

// ---------------- MLP head ----------------
__global__ void k_mlp(const float* __restrict__ fc1w, const float* __restrict__ fc1b,
                      const float* __restrict__ fc2w, const float* __restrict__ fc2b,
                      const float* __restrict__ fcw,  const float* __restrict__ fcb,
                      float* __restrict__ out) {
    __shared__ float hg[GG * 64];
    __shared__ float x1[GG * 32];
    __shared__ float x2[GG * 16];
    int tid = threadIdx.x;
    for (int i = tid; i < GG * 64; i += 256) hg[i] = g_pool[i];
    __syncthreads();
    for (int i = tid; i < GG * 32; i += 256) {
        int g = i >> 5, o = i & 31;
        float s = fc1b[o];
        for (int k = 0; k < 64; k++) s = fmaf(hg[g * 64 + k], fc1w[k * 32 + o], s);
        x1[i] = fmaxf(s, 0.f);
    }
    __syncthreads();
    for (int i = tid; i < GG * 16; i += 256) {
        int g = i >> 4, o = i & 15;
        float s = fc2b[o];
        for (int k = 0; k < 32; k++) s = fmaf(x1[g * 32 + k], fc2w[k * 16 + o], s);
        float v = fmaxf(s, 0.f);
        x2[i] = v;
        out[GG * DOUT + i] = v;
    }
    __syncthreads();
    for (int i = tid; i < GG * DOUT; i += 256) {
        int g = i / DOUT, o = i - g * DOUT;
        float s = fcb[o];
        for (int k = 0; k < 16; k++) s = fmaf(x2[g * 16 + k], fcw[k * DOUT + o], s);
        out[i] = s;
    }
}

// ---------------- launch ----------------
extern "C" void kernel_launch(void* const* d_in, const int* in_sizes, int n_in,
                              void* d_out, int out_size) {
    const float* x    = (const float*)d_in[0];
    const int*   ei   = (const int*)  d_in[1];
    const int*   bat  = (const int*)  d_in[2];
    const float* W1l  = (const float*)d_in[3];
    const float* W1r  = (const float*)d_in[4];
    const float* a1   = (const float*)d_in[5];
    const float* b1   = (const float*)d_in[6];
    const float* W2l  = (const float*)d_in[7];
    const float* W2r  = (const float*)d_in[8];
    const float* a2   = (const float*)d_in[9];
    const float* b2   = (const float*)d_in[10];
    const float* fc1w = (const float*)d_in[11];
    const float* fc1b = (const float*)d_in[12];
    const float* fc2w = (const float*)d_in[13];
    const float* fc2b = (const float*)d_in[14];
    const float* fcw  = (const float*)d_in[15];
    const float* fcb  = (const float*)d_in[16];
    float* out = (float*)d_out;

    int E = in_sizes[1] / 2;

    __half *xh, *w1t, *w2t, *xl1h, *xl2h, *h1;
    float *xr1, *xr2;
    int *deg;
    cudaGetSymbolAddress((void**)&xh,   g_xh);
    cudaGetSymbolAddress((void**)&w1t,  g_w1t);
    cudaGetSymbolAddress((void**)&w2t,  g_w2t);
    cudaGetSymbolAddress((void**)&xl1h, g_xl1h);
    cudaGetSymbolAddress((void**)&xr1,  g_xr1);
    cudaGetSymbolAddress((void**)&h1,   g_h1);
    cudaGetSymbolAddress((void**)&xl2h, g_xl2h);
    cudaGetSymbolAddress((void**)&xr2,  g_xr2);
    cudaGetSymbolAddress((void**)&deg,  g_deg);

    const int GRID_M = (NN + 127) / 128;   // 235
    const int NPREP  = NN * DIN / 8 + 2 * F1 * DIN + 2 * F2 * F1;  // + E at runtime

    cudaMemsetAsync(deg, 0, NN * sizeof(int));

    // launch 0: fused conversions + degree histogram
    k_prep<<<(NPREP + E + 255) / 256, 256>>>(x, W1l, W1r, W2l, W2r, ei, E);
    // launch 1-2: CSR
    k_scan<<<1, 1024>>>(NN);
    k_scatter<<<(E + 255) / 256, 256>>>(ei, E);

    // launch 3 (ncu capture window): layer 1 linear transforms
    k_hgemm<<<dim3(2 * F1 / 128, GRID_M), 256>>>(xh, w1t, xl1h, xr1, NN, DIN, F1);

    // layer 1 attention + aggregation (+ELU fused, fp16 out)
    k_agg1<<<(NN * 32 + 255) / 256, 256>>>(a1, b1);

    // layer 2 linear transforms (A = fp16 h1)
    k_hgemm<<<dim3(2 * F2 / 128, GRID_M), 256>>>(h1, w2t, xl2h, xr2, NN, F1, F2);

    // layer 2 attention + aggregation (+bias)
    k_agg2<<<(NN * 32 + 255) / 256, 256>>>(a2, b2);

    // pool + MLP head
    k_pool<<<GG, 256>>>(bat, NN);
    k_mlp<<<1, 256>>>(fc1w, fc1b, fc2w, fc2b, fcw, fcb, out);
}

// round 14
// speedup vs baseline: 1.2596x; 1.0289x over previous
#include <cuda_runtime.h>
#include <cuda_fp16.h>
#include <math.h>
#include <stdint.h>

// ---------------- problem constants ----------------
#define NN     30000      // nodes
#define EMAX   480000     // edges (before self loops)
#define DIN    128
#define F1     256        // H1*DH
#define F2     64         // H2*DH
#define GG     64
#define DOUT   10
#define ETOT   (EMAX + NN)

// ---------------- scratch (device globals; no allocation allowed) ----------------
__device__ __half g_xh  [NN * DIN];       // fp16 input features
__device__ __half g_w1t [2 * F1 * DIN];   // fp16 [N=512][K=128]  (W1l|W1r)^T
__device__ __half g_w2t [2 * F2 * F1];    // fp16 [N=128][K=256]  (W2l|W2r)^T
__device__ __half g_xl1h[NN * F1];        // fp16 gathered operand, layer 1
__device__ float  g_xr1 [NN * F1];
__device__ __half g_h1  [NN * F1];        // fp16: only feeds GEMM2 A
__device__ __half g_xl2h[NN * F2];        // fp16 gathered operand, layer 2
__device__ float  g_xr2 [NN * F2];
__device__ float  g_h2  [NN * F2];
__device__ int    g_deg[NN];
__device__ int    g_row[NN + 1];
__device__ int    g_cur[NN];
__device__ int    g_csr[ETOT];
__device__ float  g_pool[GG * F2];

// ---------------- mma / cp.async / ldmatrix helpers ----------------
__device__ __forceinline__ void mma_f16(float* d, const uint32_t* a, const uint32_t* b) {
    asm("mma.sync.aligned.m16n8k16.row.col.f32.f16.f16.f32 "
        "{%0,%1,%2,%3},{%4,%5,%6,%7},{%8,%9},{%0,%1,%2,%3};"
        : "+f"(d[0]), "+f"(d[1]), "+f"(d[2]), "+f"(d[3])
        : "r"(a[0]), "r"(a[1]), "r"(a[2]), "r"(a[3]), "r"(b[0]), "r"(b[1]));
}

__device__ __forceinline__ void cp16(uint32_t smem, const void* gmem) {
    asm volatile("cp.async.cg.shared.global [%0], [%1], 16;" :: "r"(smem), "l"(gmem));
}
#define CP_COMMIT()  asm volatile("cp.async.commit_group;")
#define CP_WAIT0()   asm volatile("cp.async.wait_group 0;")

__device__ __forceinline__ void ldsm4(uint32_t* r, uint32_t saddr) {
    asm volatile("ldmatrix.sync.aligned.m8n8.x4.shared.b16 {%0,%1,%2,%3}, [%4];"
        : "=r"(r[0]), "=r"(r[1]), "=r"(r[2]), "=r"(r[3]) : "r"(saddr));
}

// ---------------- fp16 single-K-shot GEMM --------------------------------
// A [M,K] fp16 row-major; Bt [Nc,K] fp16 (N-major rows of K).  Nc = 2*Nn.
// C(:, 0:Nn) -> fp16 H0 ; C(:, Nn:Nc) -> fp32 C1.
// 256 thr, BM=128, BN=128, KC=128-halves chunks; warps 2x4; warp tile 64x32.
// Row stride 272B (68 uint32): ldmatrix 8-row phases are bank-conflict-free.
// Dynamic smem 69632B: A tile then B tile. K=128 -> 1 chunk, 1 barrier total.
#define ROWU 68
#define TILEU (128 * ROWU)
__global__ void __launch_bounds__(256) k_hgemm(const __half* __restrict__ A,
                                               const __half* __restrict__ Bt,
                                               __half* __restrict__ H0,
                                               float* __restrict__ C1,
                                               int M, int K, int Nn) {
    extern __shared__ uint32_t dsm[];
    uint32_t* As = dsm;
    uint32_t* Bs = dsm + TILEU;

    int n0 = blockIdx.x * 128;
    int m0 = blockIdx.y * 128;

    int tid  = threadIdx.x;
    int wid  = tid >> 5, lane = tid & 31;
    int g    = lane >> 2, t = lane & 3;
    int wm   = wid >> 2, wn = wid & 3;      // warp grid 2x4
    int wr   = wm * 64;
    int wc   = wn * 32;

    float acc[4][4][4];
#pragma unroll
    for (int i = 0; i < 4; i++)
#pragma unroll
        for (int j = 0; j < 4; j++)
#pragma unroll
            for (int q = 0; q < 4; q++) acc[i][j][q] = 0.f;

    uint32_t sA = (uint32_t)__cvta_generic_to_shared(As);
    uint32_t sB = (uint32_t)__cvta_generic_to_shared(Bs);
    uint32_t aoff = (uint32_t)(wr + (lane & 15)) * 272u + (uint32_t)(lane >> 4) * 16u;
    uint32_t boff = (uint32_t)(wc + (lane & 7) + ((lane >> 4) << 3)) * 272u
                  + (uint32_t)((lane >> 3) & 1) * 16u;

    const int nCh = K >> 7;                  // chunks of 128 halves
    for (int ch = 0; ch < nCh; ch++) {
        int kbase = ch << 7;
        // load whole 128x128-half A and B chunks (8x cp.async each per thread)
#pragma unroll
        for (int p = 0; p < 8; p++) {
            int idx = p * 256 + tid;         // 0..2047
            int r = idx >> 4, o = idx & 15;  // row, 16B-chunk within row
            int gr = m0 + r; if (gr >= M) gr = M - 1;
            cp16(sA + (uint32_t)(r * ROWU + o * 4) * 4u,
                 A + (size_t)gr * K + kbase + o * 8);
            cp16(sB + (uint32_t)(r * ROWU + o * 4) * 4u,
                 Bt + (size_t)(n0 + r) * K + kbase + o * 8);
        }
        CP_COMMIT();
        CP_WAIT0();
        __syncthreads();

#pragma unroll
        for (int ks = 0; ks < 8; ks++) {
            uint32_t kb = (uint32_t)ks * 32u;     // 16 halves per k-step
            uint32_t af[4][4], bfr[2][4];
#pragma unroll
            for (int mt = 0; mt < 4; mt++)
                ldsm4(af[mt], sA + (uint32_t)(mt * 16) * 272u + kb + aoff);
#pragma unroll
            for (int p = 0; p < 2; p++)
                ldsm4(bfr[p], sB + (uint32_t)(p * 16) * 272u + kb + boff);
#pragma unroll
            for (int mt = 0; mt < 4; mt++)
#pragma unroll
                for (int nt = 0; nt < 4; nt++)
                    mma_f16(acc[mt][nt], af[mt], &bfr[nt >> 1][(nt & 1) * 2]);
        }
        if (ch + 1 < nCh) __syncthreads();
    }

    // epilogue: columns < Nn -> fp16 H0, else -> fp32 C1
#pragma unroll
    for (int mt = 0; mt < 4; mt++) {
        int r0 = m0 + wr + mt * 16 + g;
        int r1 = r0 + 8;
#pragma unroll
        for (int nt = 0; nt < 4; nt++) {
            int cc = n0 + wc + nt * 8 + t * 2;
            if (cc < Nn) {
                __half2 h01 = __floats2half2_rn(acc[mt][nt][0], acc[mt][nt][1]);
                __half2 h23 = __floats2half2_rn(acc[mt][nt][2], acc[mt][nt][3]);
                if (r0 < M) *(__half2*)(H0 + (size_t)r0 * Nn + cc) = h01;
                if (r1 < M) *(__half2*)(H0 + (size_t)r1 * Nn + cc) = h23;
            } else {
                int c2 = cc - Nn;
                if (r0 < M)
                    *(float2*)(C1 + (size_t)r0 * Nn + c2) = make_float2(acc[mt][nt][0], acc[mt][nt][1]);
                if (r1 < M)
                    *(float2*)(C1 + (size_t)r1 * Nn + c2) = make_float2(acc[mt][nt][2], acc[mt][nt][3]);
            }
        }
    }
}

// ---------------- fused prep: x->fp16, weights->fp16 transposed, degree hist --
__global__ void k_prep(const float* __restrict__ x,
                       const float* __restrict__ W1l, const float* __restrict__ W1r,
                       const float* __restrict__ W2l, const float* __restrict__ W2r,
                       const int* __restrict__ ei, int E) {
    const int NX  = NN * DIN / 8;          // 480000 (8 elems per thread)
    const int SZ1 = 2 * F1 * DIN;          // 65536
    const int SZ2 = 2 * F2 * F1;           // 32768
    int i = blockIdx.x * blockDim.x + threadIdx.x;
    if (i < NX) {
        float4 v0 = *(const float4*)(x + (size_t)i * 8);
        float4 v1 = *(const float4*)(x + (size_t)i * 8 + 4);
        __half2 h0 = __floats2half2_rn(v0.x, v0.y);
        __half2 h1 = __floats2half2_rn(v0.z, v0.w);
        __half2 h2 = __floats2half2_rn(v1.x, v1.y);
        __half2 h3 = __floats2half2_rn(v1.z, v1.w);
        uint4 u = make_uint4(*(uint32_t*)&h0, *(uint32_t*)&h1,
                             *(uint32_t*)&h2, *(uint32_t*)&h3);
        *(uint4*)(g_xh + (size_t)i * 8) = u;
    } else if (i < NX + SZ1) {
        int j = i - NX;
        int n = j / DIN, k = j - n * DIN;
        float v = (n < F1) ? W1l[(size_t)k * F1 + n] : W1r[(size_t)k * F1 + (n - F1)];
        g_w1t[j] = __float2half_rn(v);
    } else if (i < NX + SZ1 + SZ2) {
        int j = i - NX - SZ1;
        int n = j / F1, k = j - n * F1;
        float v = (n < F2) ? W2l[(size_t)k * F2 + n] : W2r[(size_t)k * F2 + (n - F2)];
        g_w2t[j] = __float2half_rn(v);
    } else if (i < NX + SZ1 + SZ2 + E) {
        int e = i - NX - SZ1 - SZ2;
        atomicAdd(&g_deg[ei[E + e]], 1);
    }
}

// ---------------- CSR build ----------------
// 1024-thread shuffle scan (+1 self loop folded in) fused with csr_init
__global__ void k_scan(int n) {
    __shared__ int wsum[32];
    __shared__ int carry;
    int tid = threadIdx.x, lane = tid & 31, wid = tid >> 5;
    if (tid == 0) carry = 0;
    __syncthreads();
    for (int base = 0; base < n; base += 1024) {
        int i = base + tid;
        int v = (i < n) ? (g_deg[i] + 1) : 0;     // +1 = self loop
        int incl = v;
#pragma unroll
        for (int off = 1; off < 32; off <<= 1) {
            int tt = __shfl_up_sync(0xffffffffu, incl, off);
            if (lane >= off) incl += tt;
        }
        if (lane == 31) wsum[wid] = incl;
        __syncthreads();
        if (wid == 0) {
            int s = wsum[lane];
#pragma unroll
            for (int off = 1; off < 32; off <<= 1) {
                int tt = __shfl_up_sync(0xffffffffu, s, off);
                if (lane >= off) s += tt;
            }
            wsum[lane] = s;
        }
        __syncthreads();
        int woff = wid ? wsum[wid - 1] : 0;
        int c = carry;
        if (i < n) {
            int r = c + woff + incl - v;          // exclusive
            g_row[i] = r;
            g_csr[r] = i;                          // self loop first
            g_cur[i] = r + 1;
        }
        __syncthreads();
        if (tid == 0) carry = c + wsum[31];
        __syncthreads();
    }
    if (tid == 0) g_row[n] = carry;
}

__global__ void k_scatter(const int* __restrict__ ei, int E) {
    int e = blockIdx.x * blockDim.x + threadIdx.x;
    if (e < E) {
        int dst = ei[E + e];
        int pos = atomicAdd(&g_cur[dst], 1);
        g_csr[pos] = ei[e];
    }
}

// ---------------- GATv2 aggregation, layer 1 (no-max softmax; fp16 I/O) ------
// Softmax is shift-invariant; scores are bounded (|e| <~ 10), so exp() is safe.
__global__ void k_agg1(const float* __restrict__ att, const float* __restrict__ bias) {
    int warp = (blockIdx.x * blockDim.x + threadIdx.x) >> 5;
    if (warp >= NN) return;
    int lane = threadIdx.x & 31;
    int base = (lane >> 2) * 32 + (lane & 3) * 8;

    float xr[8], av[8];
    {
        float4 r0 = *(const float4*)(g_xr1 + (size_t)warp * F1 + base);
        float4 r1 = *(const float4*)(g_xr1 + (size_t)warp * F1 + base + 4);
        xr[0]=r0.x; xr[1]=r0.y; xr[2]=r0.z; xr[3]=r0.w;
        xr[4]=r1.x; xr[5]=r1.y; xr[6]=r1.z; xr[7]=r1.w;
        float4 a0 = *(const float4*)(att + base);
        float4 a1 = *(const float4*)(att + base + 4);
        av[0]=a0.x; av[1]=a0.y; av[2]=a0.z; av[3]=a0.w;
        av[4]=a1.x; av[5]=a1.y; av[6]=a1.z; av[7]=a1.w;
    }

    float acc[8];
#pragma unroll
    for (int j = 0; j < 8; j++) acc[j] = 0.f;
    float z = 0.f;

    const __half* xb = g_xl1h + base;
    int e0 = g_row[warp], e1 = g_row[warp + 1];
    uint4 nu = *(const uint4*)(xb + (size_t)g_csr[e0] * F1);
    for (int e = e0; e < e1; e++) {
        uint4 u = nu;
        if (e + 1 < e1)
            nu = *(const uint4*)(xb + (size_t)g_csr[e + 1] * F1);
        __half2* hh = (__half2*)&u;
        float2 p0 = __half22float2(hh[0]);
        float2 p1 = __half22float2(hh[1]);
        float2 p2 = __half22float2(hh[2]);
        float2 p3 = __half22float2(hh[3]);
        float xj[8] = {p0.x, p0.y, p1.x, p1.y, p2.x, p2.y, p3.x, p3.y};
        float t = 0.f;
#pragma unroll
        for (int j = 0; j < 8; j++) {
            float v = xj[j] + xr[j];
            v = (v > 0.f) ? v : 0.2f * v;
            t = fmaf(v, av[j], t);
        }
        t += __shfl_xor_sync(0xffffffffu, t, 1);
        t += __shfl_xor_sync(0xffffffffu, t, 2);
        float w = __expf(t);
        z += w;
#pragma unroll
        for (int j = 0; j < 8; j++)
            acc[j] = fmaf(w, xj[j], acc[j]);
    }
    float inv = 1.f / z;
    float o[8];
#pragma unroll
    for (int j = 0; j < 8; j++) {
        float v = acc[j] * inv + bias[base + j];
        o[j] = (v > 0.f) ? v : expm1f(v);          // ELU fused
    }
    __half2 h0 = __floats2half2_rn(o[0], o[1]);
    __half2 h1 = __floats2half2_rn(o[2], o[3]);
    __half2 h2 = __floats2half2_rn(o[4], o[5]);
    __half2 h3 = __floats2half2_rn(o[6], o[7]);
    uint4 uo = make_uint4(*(uint32_t*)&h0, *(uint32_t*)&h1,
                          *(uint32_t*)&h2, *(uint32_t*)&h3);
    *(uint4*)(g_h1 + (size_t)warp * F1 + base) = uo;
}

// ---------------- GATv2 aggregation, layer 2 (no-max softmax; fp16 gather) ---
__global__ void k_agg2(const float* __restrict__ att, const float* __restrict__ bias) {
    int warp = (blockIdx.x * blockDim.x + threadIdx.x) >> 5;
    if (warp >= NN) return;
    int lane = threadIdx.x & 31;
    int base = (lane >> 4) * 32 + (lane & 15) * 2;

    float2 xr = *(const float2*)(g_xr2 + (size_t)warp * F2 + base);
    float2 av = *(const float2*)(att + base);

    float acc0 = 0.f, acc1 = 0.f, z = 0.f;

    const __half* xb = g_xl2h + base;
    int e0 = g_row[warp], e1 = g_row[warp + 1];
    __half2 nx = *(const __half2*)(xb + (size_t)g_csr[e0] * F2);
    for (int e = e0; e < e1; e++) {
        float2 xj = __half22float2(nx);
        if (e + 1 < e1)
            nx = *(const __half2*)(xb + (size_t)g_csr[e + 1] * F2);
        float v0 = xj.x + xr.x; v0 = (v0 > 0.f) ? v0 : 0.2f * v0;
        float v1 = xj.y + xr.y; v1 = (v1 > 0.f) ? v1 : 0.2f * v1;
        float t = fmaf(v0, av.x, v1 * av.y);
        t += __shfl_xor_sync(0xffffffffu, t, 1);
        t += __shfl_xor_sync(0xffffffffu, t, 2);
        t += __shfl_xor_sync(0xffffffffu, t, 4);
        t += __shfl_xor_sync(0xffffffffu, t, 8);
        float w = __expf(t);
        z += w;
        acc0 = fmaf(w, xj.x, acc0);
        acc1 = fmaf(w, xj.y, acc1);
    }
    float inv = 1.f / z;
    g_h2[(size_t)warp * F2 + base + 0] = acc0 * inv + bias[base + 0];
    g_h2[(size_t)warp * F2 + base + 1] = acc1 * inv + bias[base + 1];
}

// ---------------- mean pool over sorted batch ----------------
__device__ __forceinline__ int lb(const int* b, int n, int g) {
    int lo = 0, hi = n;
    while (lo < hi) { int mid = (lo + hi) >> 1; if (b[mid] < g) lo = mid + 1; else hi = mid; }
    return lo;
}

__global__ void k_pool(const int* __restrict__ batch, int n) {
    __shared__ float part[4][64];
    int g = blockIdx.x;
    int d = threadIdx.x & 63;
    int ty = threadIdx.x >> 6;
    int s = lb(batch, n, g);
    int e = lb(batch, n, g + 1);
    float sum = 0.f;
    for (int i = s + ty; i < e; i += 4) sum += g_h2[(size_t)i * F2 + d];
    part[ty][d] = sum;
    __syncthreads();
    if (ty == 0) {
        float tot = part[0][d] + part[1][d] + part[2][d] + part[3][d];
        int cnt = e - s; if (cnt < 1) cnt = 1;
        g_pool[g * F2 + d] = tot / (float)cnt;
    }
}

// ---------------- MLP head ----------------
__global__ void k_mlp(const float* __restrict__ fc1w, const float* __restrict__ fc1b,
                      const float* __restrict__ fc2w, const float* __restrict__ fc2b,
                      const float* __restrict__ fcw,  const float* __restrict__ fcb,
                      float* __restrict__ out) {
    __shared__ float hg[GG * 64];
    __shared__ float x1[GG * 32];
    __shared__ float x2[GG * 16];
    int tid = threadIdx.x;
    for (int i = tid; i < GG * 64; i += 256) hg[i] = g_pool[i];
    __syncthreads();
    for (int i = tid; i < GG * 32; i += 256) {
        int g = i >> 5, o = i & 31;
        float s = fc1b[o];
        for (int k = 0; k < 64; k++) s = fmaf(hg[g * 64 + k], fc1w[k * 32 + o], s);
        x1[i] = fmaxf(s, 0.f);
    }
    __syncthreads();
    for (int i = tid; i < GG * 16; i += 256) {
        int g = i >> 4, o = i & 15;
        float s = fc2b[o];
        for (int k = 0; k < 32; k++) s = fmaf(x1[g * 32 + k], fc2w[k * 16 + o], s);
        float v = fmaxf(s, 0.f);
        x2[i] = v;
        out[GG * DOUT + i] = v;
    }
    __syncthreads();
    for (int i = tid; i < GG * DOUT; i += 256) {
        int g = i / DOUT, o = i - g * DOUT;
        float s = fcb[o];
        for (int k = 0; k < 16; k++) s = fmaf(x2[g * 16 + k], fcw[k * DOUT + o], s);
        out[i] = s;
    }
}

// ---------------- launch ----------------
extern "C" void kernel_launch(void* const* d_in, const int* in_sizes, int n_in,
                              void* d_out, int out_size) {
    const float* x    = (const float*)d_in[0];
    const int*   ei   = (const int*)  d_in[1];
    const int*   bat  = (const int*)  d_in[2];
    const float* W1l  = (const float*)d_in[3];
    const float* W1r  = (const float*)d_in[4];
    const float* a1   = (const float*)d_in[5];
    const float* b1   = (const float*)d_in[6];
    const float* W2l  = (const float*)d_in[7];
    const float* W2r  = (const float*)d_in[8];
    const float* a2   = (const float*)d_in[9];
    const float* b2   = (const float*)d_in[10];
    const float* fc1w = (const float*)d_in[11];
    const float* fc1b = (const float*)d_in[12];
    const float* fc2w = (const float*)d_in[13];
    const float* fc2b = (const float*)d_in[14];
    const float* fcw  = (const float*)d_in[15];
    const float* fcb  = (const float*)d_in[16];
    float* out = (float*)d_out;

    int E = in_sizes[1] / 2;

    __half *xh, *w1t, *w2t, *xl1h, *xl2h, *h1;
    float *xr1, *xr2;
    int *deg;
    cudaGetSymbolAddress((void**)&xh,   g_xh);
    cudaGetSymbolAddress((void**)&w1t,  g_w1t);
    cudaGetSymbolAddress((void**)&w2t,  g_w2t);
    cudaGetSymbolAddress((void**)&xl1h, g_xl1h);
    cudaGetSymbolAddress((void**)&xr1,  g_xr1);
    cudaGetSymbolAddress((void**)&h1,   g_h1);
    cudaGetSymbolAddress((void**)&xl2h, g_xl2h);
    cudaGetSymbolAddress((void**)&xr2,  g_xr2);
    cudaGetSymbolAddress((void**)&deg,  g_deg);

    const int GRID_M = (NN + 127) / 128;   // 235
    const int NPREP  = NN * DIN / 8 + 2 * F1 * DIN + 2 * F2 * F1;  // + E at runtime
    const int SMEMSZ = 2 * TILEU * 4;      // 69632 B

    cudaFuncSetAttribute(k_hgemm, cudaFuncAttributeMaxDynamicSharedMemorySize, SMEMSZ);
    cudaMemsetAsync(deg, 0, NN * sizeof(int));

    // launch 0: fused conversions + degree histogram
    k_prep<<<(NPREP + E + 255) / 256, 256>>>(x, W1l, W1r, W2l, W2r, ei, E);
    // launch 1-2: CSR
    k_scan<<<1, 1024>>>(NN);
    k_scatter<<<(E + 255) / 256, 256>>>(ei, E);

    // launch 3 (ncu capture window): layer 1 linear transforms
    k_hgemm<<<dim3(2 * F1 / 128, GRID_M), 256, SMEMSZ>>>(xh, w1t, xl1h, xr1, NN, DIN, F1);

    // layer 1 attention + aggregation (+ELU fused, fp16 out)
    k_agg1<<<(NN * 32 + 255) / 256, 256>>>(a1, b1);

    // layer 2 linear transforms (A = fp16 h1)
    k_hgemm<<<dim3(2 * F2 / 128, GRID_M), 256, SMEMSZ>>>(h1, w2t, xl2h, xr2, NN, F1, F2);

    // layer 2 attention + aggregation (+bias)
    k_agg2<<<(NN * 32 + 255) / 256, 256>>>(a2, b2);

    // pool + MLP head
    k_pool<<<GG, 256>>>(bat, NN);
    k_mlp<<<1, 256>>>(fc1w, fc1b, fc2w, fc2b, fcw, fcb, out);
}